// round 2
// baseline (speedup 1.0000x reference)
#include <cuda_runtime.h>
#include <cstdint>

#define T_DIM 2048
#define C_DIM 1024
#define NHEAD 16
#define HDIM  64
#define QKV_N (3 * C_DIM)

// Scratch (allocation-free rule: __device__ globals)
__device__ float g_qkv[T_DIM * QKV_N];   // (T, 3C)
__device__ float g_z[T_DIM * C_DIM];     // permuted y, ready for proj GEMM

// ---------------------------------------------------------------------------
// NT GEMM + bias: C[m,n] = sum_k A[m,k]*B[n,k] + bias[n]
// A: (M,K) row-major, B: (N,K) row-major. Tiles 128x128x16, 8x8 microtile.
// ---------------------------------------------------------------------------
__global__ __launch_bounds__(256) void gemm_nt_bias(
    const float* __restrict__ A, const float* __restrict__ B,
    const float* __restrict__ bias, float* __restrict__ C,
    int M, int N, int K)
{
    __shared__ float As[16][132];
    __shared__ float Bs[16][132];
    const int tid = threadIdx.x;
    const int tx = tid & 15, ty = tid >> 4;
    const int bm = blockIdx.y * 128, bn = blockIdx.x * 128;

    float acc[8][8];
    #pragma unroll
    for (int i = 0; i < 8; i++)
        #pragma unroll
        for (int j = 0; j < 8; j++) acc[i][j] = 0.f;

    for (int k0 = 0; k0 < K; k0 += 16) {
        #pragma unroll
        for (int s = tid; s < 512; s += 256) {
            int m = s >> 2, k4 = s & 3;
            float4 v = *(const float4*)(A + (size_t)(bm + m) * K + k0 + k4 * 4);
            As[k4*4+0][m] = v.x; As[k4*4+1][m] = v.y;
            As[k4*4+2][m] = v.z; As[k4*4+3][m] = v.w;
        }
        #pragma unroll
        for (int s = tid; s < 512; s += 256) {
            int n = s >> 2, k4 = s & 3;
            float4 v = *(const float4*)(B + (size_t)(bn + n) * K + k0 + k4 * 4);
            Bs[k4*4+0][n] = v.x; Bs[k4*4+1][n] = v.y;
            Bs[k4*4+2][n] = v.z; Bs[k4*4+3][n] = v.w;
        }
        __syncthreads();
        #pragma unroll
        for (int k = 0; k < 16; k++) {
            float a[8], b[8];
            *(float4*)(a)     = *(const float4*)&As[k][ty*8];
            *(float4*)(a + 4) = *(const float4*)&As[k][ty*8 + 4];
            *(float4*)(b)     = *(const float4*)&Bs[k][tx*8];
            *(float4*)(b + 4) = *(const float4*)&Bs[k][tx*8 + 4];
            #pragma unroll
            for (int i = 0; i < 8; i++)
                #pragma unroll
                for (int j = 0; j < 8; j++)
                    acc[i][j] += a[i] * b[j];
        }
        __syncthreads();
    }

    float bb[8];
    *(float4*)(bb)     = *(const float4*)(bias + bn + tx*8);
    *(float4*)(bb + 4) = *(const float4*)(bias + bn + tx*8 + 4);
    #pragma unroll
    for (int i = 0; i < 8; i++) {
        float* cp = C + (size_t)(bm + ty*8 + i) * N + bn + tx*8;
        float4 o0 = make_float4(acc[i][0]+bb[0], acc[i][1]+bb[1],
                                acc[i][2]+bb[2], acc[i][3]+bb[3]);
        float4 o1 = make_float4(acc[i][4]+bb[4], acc[i][5]+bb[5],
                                acc[i][6]+bb[6], acc[i][7]+bb[7]);
        *(float4*)(cp)     = o0;
        *(float4*)(cp + 4) = o1;
    }
}

// ---------------------------------------------------------------------------
// Flash-style causal attention. One block = (head h, 64-query tile qt).
// 256 threads as 16x16; each thread owns a 4x4 patch of the 64x64 (q x k) /
// (q x d) tiles. Online softmax; stats replicated across the 16 lanes that
// share a row (shfl width-16 reductions).
// Epilogue writes straight into the reference's buggy reshape layout:
//   Z[h*128 + 2*d + (t>>10)][t & 1023] = y[h][t][d]
// ---------------------------------------------------------------------------
__global__ __launch_bounds__(256) void attn_kernel(
    const float* __restrict__ qkv, float* __restrict__ Z)
{
    extern __shared__ float sm[];
    float* QsT = sm;                 // [64 d][64 r]  (transposed)
    float* KsT = sm + 4096;          // [64 d][64 c]  (transposed)
    float* Vs  = sm + 8192;          // [64 j][64 d]
    float* Ps  = sm + 12288;         // [64 r][64 j]

    const int tid = threadIdx.x;
    const int tx = tid & 15, ty = tid >> 4;
    const int qt = (int)gridDim.x - 1 - (int)blockIdx.x;  // long blocks first
    const int h  = blockIdx.y;

    const float* qbase = qkv + h * HDIM;
    const float* kbase = qkv + C_DIM     + h * HDIM;
    const float* vbase = qkv + 2 * C_DIM + h * HDIM;

    // Load Q tile transposed: QsT[d][r]
    #pragma unroll
    for (int s = tid; s < 1024; s += 256) {
        int r = s >> 4, d4 = s & 15;
        float4 v = *(const float4*)(qbase + (size_t)(qt*64 + r) * QKV_N + d4*4);
        QsT[(d4*4+0)*64 + r] = v.x; QsT[(d4*4+1)*64 + r] = v.y;
        QsT[(d4*4+2)*64 + r] = v.z; QsT[(d4*4+3)*64 + r] = v.w;
    }

    float m_run[4] = {-1e30f, -1e30f, -1e30f, -1e30f};
    float l_run[4] = {0.f, 0.f, 0.f, 0.f};
    float acc[4][4];
    #pragma unroll
    for (int i = 0; i < 4; i++)
        #pragma unroll
        for (int j = 0; j < 4; j++) acc[i][j] = 0.f;

    for (int kt = 0; kt <= qt; kt++) {
        __syncthreads();   // previous iteration's consumers done
        // Load K (transposed) + V tiles
        #pragma unroll
        for (int s = tid; s < 1024; s += 256) {
            int c = s >> 4, d4 = s & 15;
            size_t row = (size_t)(kt*64 + c) * QKV_N + d4*4;
            float4 kv = *(const float4*)(kbase + row);
            KsT[(d4*4+0)*64 + c] = kv.x; KsT[(d4*4+1)*64 + c] = kv.y;
            KsT[(d4*4+2)*64 + c] = kv.z; KsT[(d4*4+3)*64 + c] = kv.w;
            float4 vv = *(const float4*)(vbase + row);
            *(float4*)&Vs[c*64 + d4*4] = vv;
        }
        __syncthreads();

        // S = Q K^T * 1/sqrt(HD)
        float s4[4][4];
        #pragma unroll
        for (int i = 0; i < 4; i++)
            #pragma unroll
            for (int j = 0; j < 4; j++) s4[i][j] = 0.f;
        #pragma unroll
        for (int d = 0; d < 64; d++) {
            float4 a = *(const float4*)&QsT[d*64 + ty*4];
            float4 b = *(const float4*)&KsT[d*64 + tx*4];
            float av[4] = {a.x, a.y, a.z, a.w};
            float bv[4] = {b.x, b.y, b.z, b.w};
            #pragma unroll
            for (int i = 0; i < 4; i++)
                #pragma unroll
                for (int j = 0; j < 4; j++)
                    s4[i][j] += av[i] * bv[j];
        }
        #pragma unroll
        for (int i = 0; i < 4; i++)
            #pragma unroll
            for (int j = 0; j < 4; j++) s4[i][j] *= 0.125f;

        if (kt == qt) {  // causal mask on the diagonal tile
            #pragma unroll
            for (int i = 0; i < 4; i++)
                #pragma unroll
                for (int j = 0; j < 4; j++)
                    if (tx*4 + j > ty*4 + i) s4[i][j] = -1e30f;
        }

        // Online softmax update (row stats replicated across 16 lanes)
        #pragma unroll
        for (int i = 0; i < 4; i++) {
            float mx = fmaxf(fmaxf(s4[i][0], s4[i][1]), fmaxf(s4[i][2], s4[i][3]));
            #pragma unroll
            for (int off = 1; off < 16; off <<= 1)
                mx = fmaxf(mx, __shfl_xor_sync(0xffffffffu, mx, off));
            float mn = fmaxf(m_run[i], mx);
            float alpha = __expf(m_run[i] - mn);
            float psum = 0.f;
            #pragma unroll
            for (int j = 0; j < 4; j++) {
                float p = __expf(s4[i][j] - mn);
                s4[i][j] = p;
                psum += p;
            }
            #pragma unroll
            for (int off = 1; off < 16; off <<= 1)
                psum += __shfl_xor_sync(0xffffffffu, psum, off);
            l_run[i] = l_run[i] * alpha + psum;
            m_run[i] = mn;
            #pragma unroll
            for (int j = 0; j < 4; j++) acc[i][j] *= alpha;
        }

        // Stage P to smem
        #pragma unroll
        for (int i = 0; i < 4; i++)
            *(float4*)&Ps[(ty*4 + i)*64 + tx*4] =
                make_float4(s4[i][0], s4[i][1], s4[i][2], s4[i][3]);
        __syncthreads();

        // O += P V
        #pragma unroll
        for (int jk = 0; jk < 64; jk += 4) {
            float pr[4][4];
            #pragma unroll
            for (int i = 0; i < 4; i++)
                *(float4*)pr[i] = *(const float4*)&Ps[(ty*4 + i)*64 + jk];
            #pragma unroll
            for (int jj = 0; jj < 4; jj++) {
                float4 vv = *(const float4*)&Vs[(jk + jj)*64 + tx*4];
                float vvv[4] = {vv.x, vv.y, vv.z, vv.w};
                #pragma unroll
                for (int i = 0; i < 4; i++)
                    #pragma unroll
                    for (int j = 0; j < 4; j++)
                        acc[i][j] += pr[i][jj] * vvv[j];
            }
        }
    }

    // Epilogue: normalize + scatter into the bug-faithful Z layout
    #pragma unroll
    for (int i = 0; i < 4; i++) {
        float inv = 1.0f / l_run[i];
        int t   = qt*64 + ty*4 + i;
        int col = t & (C_DIM - 1);
        int thi = t >> 10;
        #pragma unroll
        for (int j = 0; j < 4; j++) {
            int d = tx*4 + j;
            int row = h * 128 + 2*d + thi;
            Z[(size_t)row * C_DIM + col] = acc[i][j] * inv;
        }
    }
}

// ---------------------------------------------------------------------------
extern "C" void kernel_launch(void* const* d_in, const int* in_sizes, int n_in,
                              void* d_out, int out_size)
{
    const float* x      = (const float*)d_in[0];
    const float* w_attn = (const float*)d_in[1];
    const float* b_attn = (const float*)d_in[2];
    const float* w_proj = (const float*)d_in[3];
    const float* b_proj = (const float*)d_in[4];
    float* out = (float*)d_out;

    void* p_qkv; cudaGetSymbolAddress(&p_qkv, g_qkv);
    void* p_z;   cudaGetSymbolAddress(&p_z,   g_z);
    float* qkv = (float*)p_qkv;
    float* z   = (float*)p_z;

    // 1) QKV projection: (2048,3072) = x @ w_attn^T + b_attn
    {
        dim3 grid(QKV_N / 128, T_DIM / 128);
        gemm_nt_bias<<<grid, 256>>>(x, w_attn, b_attn, qkv, T_DIM, QKV_N, C_DIM);
    }

    // 2) Causal attention, fused permute into Z
    {
        const int smem = 4 * 64 * 64 * sizeof(float);  // 64 KB dynamic
        cudaFuncSetAttribute(attn_kernel,
                             cudaFuncAttributeMaxDynamicSharedMemorySize, smem);
        dim3 grid(T_DIM / 64, NHEAD);
        attn_kernel<<<grid, 256, smem>>>(qkv, z);
    }

    // 3) Output projection: (2048,1024) = Z @ w_proj^T + b_proj
    {
        dim3 grid(C_DIM / 128, T_DIM / 128);
        gemm_nt_bias<<<grid, 256>>>(z, w_proj, b_proj, out, T_DIM, C_DIM, C_DIM);
    }
}

// round 5
// speedup vs baseline: 1.4736x; 1.4736x over previous
#include <cuda_runtime.h>
#include <cuda_bf16.h>
#include <cstdint>

#define T_DIM 2048
#define C_DIM 1024
#define NHEAD 16
#define HDIM  64
#define QKV_N (3 * C_DIM)

// ---------------------------------------------------------------------------
// Scratch (__device__ globals; allocation-free rule)
// ---------------------------------------------------------------------------
__device__ float g_qkv[T_DIM * QKV_N];                  // (T, 3C) fp32
__device__ __nv_bfloat16 g_xh[T_DIM * C_DIM],  g_xl[T_DIM * C_DIM];
__device__ __nv_bfloat16 g_wah[QKV_N * C_DIM], g_wal[QKV_N * C_DIM];
__device__ __nv_bfloat16 g_wph[C_DIM * C_DIM], g_wpl[C_DIM * C_DIM];
__device__ __nv_bfloat16 g_zh[T_DIM * C_DIM],  g_zl[T_DIM * C_DIM];

// ---------------------------------------------------------------------------
// PTX helpers — ONLY sm_80-era instructions (harness stages PTX at compute_103,
// which rejects all tcgen05/103a-gated features).
// ---------------------------------------------------------------------------
__device__ __forceinline__ uint32_t smem_u32(const void* p) {
    uint32_t a;
    asm("{ .reg .u64 t; cvta.to.shared.u64 t, %1; cvt.u32.u64 %0, t; }"
        : "=r"(a) : "l"(p));
    return a;
}
__device__ __forceinline__ void cp_async16(uint32_t s, const void* g) {
    asm volatile("cp.async.cg.shared.global [%0], [%1], 16;" :: "r"(s), "l"(g));
}
#define CP_COMMIT() asm volatile("cp.async.commit_group;" ::: "memory")
#define CP_WAIT1()  asm volatile("cp.async.wait_group 1;" ::: "memory")
#define CP_WAIT0()  asm volatile("cp.async.wait_group 0;" ::: "memory")

#define LDM4(R, addr) \
    asm volatile("ldmatrix.sync.aligned.m8n8.x4.shared.b16 {%0,%1,%2,%3}, [%4];" \
        : "=r"((R)[0]), "=r"((R)[1]), "=r"((R)[2]), "=r"((R)[3]) : "r"(addr))

#define MMA16816(c, a, b0, b1) \
    asm volatile("mma.sync.aligned.m16n8k16.row.col.f32.bf16.bf16.f32 " \
        "{%0,%1,%2,%3}, {%4,%5,%6,%7}, {%8,%9}, {%0,%1,%2,%3};" \
        : "+f"((c)[0]), "+f"((c)[1]), "+f"((c)[2]), "+f"((c)[3]) \
        : "r"((a)[0]), "r"((a)[1]), "r"((a)[2]), "r"((a)[3]), "r"(b0), "r"(b1))

// ---------------------------------------------------------------------------
// fp32 -> (hi, lo) bf16 split
// ---------------------------------------------------------------------------
__global__ __launch_bounds__(256) void split_f32(
    const float* __restrict__ src, __nv_bfloat16* __restrict__ hi,
    __nv_bfloat16* __restrict__ lo, int n)
{
    int i = (blockIdx.x * 256 + threadIdx.x) * 4;
    if (i >= n) return;
    float4 v = *(const float4*)(src + i);
    float vv[4] = {v.x, v.y, v.z, v.w};
    #pragma unroll
    for (int j = 0; j < 4; j++) {
        __nv_bfloat16 h = __float2bfloat16(vv[j]);
        hi[i + j] = h;
        lo[i + j] = __float2bfloat16(vv[j] - __bfloat162float(h));
    }
}

// ---------------------------------------------------------------------------
// mma.sync NT GEMM, bf16 3-pass split + bias.
// C[m,n] = sum_k A[m,k]*B[n,k] + bias[n].
// 128x128 CTA tile, 64-k chunks, cp.async double buffer, 16 warps (4x4),
// each warp a 32x32 tile of m16n8k16 atoms, fp32 register accumulators.
// A smem: (128 rows x 72 bf16) per matrix (pad 8 -> 144B pitch, 16B aligned,
// conflict-staggered for ldmatrix). B identical (rows = n, k-contiguous, which
// feeds the col-major B fragment via non-trans ldmatrix).
// ---------------------------------------------------------------------------
__global__ __launch_bounds__(512, 1) void gemm_mma_bf16x3(
    const __nv_bfloat16* __restrict__ Ahi, const __nv_bfloat16* __restrict__ Alo,
    const __nv_bfloat16* __restrict__ Bhi, const __nv_bfloat16* __restrict__ Blo,
    const float* __restrict__ bias, float* __restrict__ C,
    int M, int N, int K)
{
    constexpr int PITCHB = 144;               // bytes per smem row (64+8 bf16)
    constexpr int MAT    = 128 * PITCHB;      // 18432 B per matrix
    constexpr int OFF_AH = 0;
    constexpr int OFF_AL = MAT;
    constexpr int OFF_BH = 2 * MAT;
    constexpr int OFF_BL = 3 * MAT;
    constexpr int STAGE  = 4 * MAT;           // 73728 B

    extern __shared__ char smem[];
    const uint32_t base = smem_u32(smem);

    const int tid  = threadIdx.x;
    const int warp = tid >> 5, lane = tid & 31;
    const int wm = warp & 3, wn = warp >> 2;
    const int bm = blockIdx.y * 128, bn = blockIdx.x * 128;

    // ldmatrix lane address components
    const uint32_t a_row = (uint32_t)(wm * 32 + ((lane >> 3) & 1) * 8 + (lane & 7));
    const uint32_t a_ko  = (uint32_t)((lane >> 4) * 8);
    const uint32_t b_row = (uint32_t)(wn * 32 + (lane >> 4) * 8 + (lane & 7));
    const uint32_t b_ko  = (uint32_t)(((lane >> 3) & 1) * 8);

    // chunk loader: 4 matrices x 1024 16B segments, 2 segs/thread/matrix
    auto load_chunk = [&](int c) {
        const uint32_t st = base + (uint32_t)(c & 1) * STAGE;
        const int k0 = c * 64;
        #pragma unroll
        for (int j = 0; j < 2; j++) {
            int g = tid + 512 * j;          // 0..1023
            int r = g >> 3, sg = g & 7;
            uint32_t so = (uint32_t)(r * PITCHB + sg * 16);
            size_t ga = (size_t)(bm + r) * K + k0 + sg * 8;
            size_t gb = (size_t)(bn + r) * K + k0 + sg * 8;
            cp_async16(st + OFF_AH + so, Ahi + ga);
            cp_async16(st + OFF_AL + so, Alo + ga);
            cp_async16(st + OFF_BH + so, Bhi + gb);
            cp_async16(st + OFF_BL + so, Blo + gb);
        }
        CP_COMMIT();
    };

    float acc[2][4][4];
    #pragma unroll
    for (int mi = 0; mi < 2; mi++)
        #pragma unroll
        for (int ni = 0; ni < 4; ni++)
            #pragma unroll
            for (int q = 0; q < 4; q++) acc[mi][ni][q] = 0.f;

    const int nch = K / 64;
    load_chunk(0);

    for (int c = 0; c < nch; c++) {
        if (c + 1 < nch) { load_chunk(c + 1); CP_WAIT1(); }
        else             { CP_WAIT0(); }
        __syncthreads();

        const uint32_t st = base + (uint32_t)(c & 1) * STAGE;
        #pragma unroll
        for (int ks = 0; ks < 4; ks++) {
            uint32_t Ah[2][4], Al[2][4], Bh[2][4], Bl[2][4];
            #pragma unroll
            for (int mi = 0; mi < 2; mi++) {
                uint32_t ao = (a_row + mi * 16) * PITCHB + (ks * 16 + a_ko) * 2;
                LDM4(Ah[mi], st + OFF_AH + ao);
                LDM4(Al[mi], st + OFF_AL + ao);
            }
            #pragma unroll
            for (int nt = 0; nt < 2; nt++) {
                uint32_t bo = (b_row + nt * 16) * PITCHB + (ks * 16 + b_ko) * 2;
                LDM4(Bh[nt], st + OFF_BH + bo);
                LDM4(Bl[nt], st + OFF_BL + bo);
            }
            #pragma unroll
            for (int mi = 0; mi < 2; mi++)
                #pragma unroll
                for (int ni = 0; ni < 4; ni++) {
                    const uint32_t bh0 = Bh[ni >> 1][(ni & 1) * 2];
                    const uint32_t bh1 = Bh[ni >> 1][(ni & 1) * 2 + 1];
                    const uint32_t bl0 = Bl[ni >> 1][(ni & 1) * 2];
                    const uint32_t bl1 = Bl[ni >> 1][(ni & 1) * 2 + 1];
                    MMA16816(acc[mi][ni], Ah[mi], bh0, bh1);
                    MMA16816(acc[mi][ni], Ah[mi], bl0, bl1);
                    MMA16816(acc[mi][ni], Al[mi], bh0, bh1);
                }
        }
        __syncthreads();
    }

    // Epilogue: fused bias, direct fp32 stores
    const int r0 = bm + wm * 32 + (lane >> 2);
    const int c0 = bn + wn * 32 + (lane & 3) * 2;
    #pragma unroll
    for (int mi = 0; mi < 2; mi++)
        #pragma unroll
        for (int ni = 0; ni < 4; ni++) {
            int row = r0 + mi * 16;
            int col = c0 + ni * 8;
            float2 b2 = *(const float2*)(bias + col);
            float2 o0 = make_float2(acc[mi][ni][0] + b2.x, acc[mi][ni][1] + b2.y);
            float2 o1 = make_float2(acc[mi][ni][2] + b2.x, acc[mi][ni][3] + b2.y);
            *(float2*)(C + (size_t)row * N + col)       = o0;
            *(float2*)(C + (size_t)(row + 8) * N + col) = o1;
        }
}

// ---------------------------------------------------------------------------
// Flash-style causal attention (proven fp32 path); epilogue emits bf16 hi/lo
// for the proj GEMM, scattered into the bug-faithful reshape layout:
//   Z[h*128 + 2*d + (t>>10)][t & 1023] = y[h][t][d]
// ---------------------------------------------------------------------------
__global__ __launch_bounds__(256) void attn_kernel(
    const float* __restrict__ qkv,
    __nv_bfloat16* __restrict__ Zhi, __nv_bfloat16* __restrict__ Zlo)
{
    extern __shared__ float sm[];
    float* QsT = sm;
    float* KsT = sm + 4096;
    float* Vs  = sm + 8192;
    float* Ps  = sm + 12288;

    const int tid = threadIdx.x;
    const int tx = tid & 15, ty = tid >> 4;
    const int qt = (int)gridDim.x - 1 - (int)blockIdx.x;
    const int h  = blockIdx.y;

    const float* qbase = qkv + h * HDIM;
    const float* kbase = qkv + C_DIM     + h * HDIM;
    const float* vbase = qkv + 2 * C_DIM + h * HDIM;

    #pragma unroll
    for (int s = tid; s < 1024; s += 256) {
        int r = s >> 4, d4 = s & 15;
        float4 v = *(const float4*)(qbase + (size_t)(qt*64 + r) * QKV_N + d4*4);
        QsT[(d4*4+0)*64 + r] = v.x; QsT[(d4*4+1)*64 + r] = v.y;
        QsT[(d4*4+2)*64 + r] = v.z; QsT[(d4*4+3)*64 + r] = v.w;
    }

    float m_run[4] = {-1e30f, -1e30f, -1e30f, -1e30f};
    float l_run[4] = {0.f, 0.f, 0.f, 0.f};
    float acc[4][4];
    #pragma unroll
    for (int i = 0; i < 4; i++)
        #pragma unroll
        for (int j = 0; j < 4; j++) acc[i][j] = 0.f;

    for (int kt = 0; kt <= qt; kt++) {
        __syncthreads();
        #pragma unroll
        for (int s = tid; s < 1024; s += 256) {
            int c = s >> 4, d4 = s & 15;
            size_t row = (size_t)(kt*64 + c) * QKV_N + d4*4;
            float4 kv = *(const float4*)(kbase + row);
            KsT[(d4*4+0)*64 + c] = kv.x; KsT[(d4*4+1)*64 + c] = kv.y;
            KsT[(d4*4+2)*64 + c] = kv.z; KsT[(d4*4+3)*64 + c] = kv.w;
            float4 vv = *(const float4*)(vbase + row);
            *(float4*)&Vs[c*64 + d4*4] = vv;
        }
        __syncthreads();

        float s4[4][4];
        #pragma unroll
        for (int i = 0; i < 4; i++)
            #pragma unroll
            for (int j = 0; j < 4; j++) s4[i][j] = 0.f;
        #pragma unroll
        for (int d = 0; d < 64; d++) {
            float4 a = *(const float4*)&QsT[d*64 + ty*4];
            float4 b = *(const float4*)&KsT[d*64 + tx*4];
            float av[4] = {a.x, a.y, a.z, a.w};
            float bv[4] = {b.x, b.y, b.z, b.w};
            #pragma unroll
            for (int i = 0; i < 4; i++)
                #pragma unroll
                for (int j = 0; j < 4; j++)
                    s4[i][j] += av[i] * bv[j];
        }
        #pragma unroll
        for (int i = 0; i < 4; i++)
            #pragma unroll
            for (int j = 0; j < 4; j++) s4[i][j] *= 0.125f;

        if (kt == qt) {
            #pragma unroll
            for (int i = 0; i < 4; i++)
                #pragma unroll
                for (int j = 0; j < 4; j++)
                    if (tx*4 + j > ty*4 + i) s4[i][j] = -1e30f;
        }

        #pragma unroll
        for (int i = 0; i < 4; i++) {
            float mx = fmaxf(fmaxf(s4[i][0], s4[i][1]), fmaxf(s4[i][2], s4[i][3]));
            #pragma unroll
            for (int off = 1; off < 16; off <<= 1)
                mx = fmaxf(mx, __shfl_xor_sync(0xffffffffu, mx, off));
            float mn = fmaxf(m_run[i], mx);
            float alpha = __expf(m_run[i] - mn);
            float psum = 0.f;
            #pragma unroll
            for (int j = 0; j < 4; j++) {
                float p = __expf(s4[i][j] - mn);
                s4[i][j] = p;
                psum += p;
            }
            #pragma unroll
            for (int off = 1; off < 16; off <<= 1)
                psum += __shfl_xor_sync(0xffffffffu, psum, off);
            l_run[i] = l_run[i] * alpha + psum;
            m_run[i] = mn;
            #pragma unroll
            for (int j = 0; j < 4; j++) acc[i][j] *= alpha;
        }

        #pragma unroll
        for (int i = 0; i < 4; i++)
            *(float4*)&Ps[(ty*4 + i)*64 + tx*4] =
                make_float4(s4[i][0], s4[i][1], s4[i][2], s4[i][3]);
        __syncthreads();

        #pragma unroll
        for (int jk = 0; jk < 64; jk += 4) {
            float pr[4][4];
            #pragma unroll
            for (int i = 0; i < 4; i++)
                *(float4*)pr[i] = *(const float4*)&Ps[(ty*4 + i)*64 + jk];
            #pragma unroll
            for (int jj = 0; jj < 4; jj++) {
                float4 vv = *(const float4*)&Vs[(jk + jj)*64 + tx*4];
                float vvv[4] = {vv.x, vv.y, vv.z, vv.w};
                #pragma unroll
                for (int i = 0; i < 4; i++)
                    #pragma unroll
                    for (int j = 0; j < 4; j++)
                        acc[i][j] += pr[i][jj] * vvv[j];
            }
        }
    }

    #pragma unroll
    for (int i = 0; i < 4; i++) {
        float inv = 1.0f / l_run[i];
        int t   = qt*64 + ty*4 + i;
        int col = t & (C_DIM - 1);
        int thi = t >> 10;
        #pragma unroll
        for (int j = 0; j < 4; j++) {
            int d = tx*4 + j;
            int row = h * 128 + 2*d + thi;
            float v = acc[i][j] * inv;
            __nv_bfloat16 hh = __float2bfloat16(v);
            size_t idx = (size_t)row * C_DIM + col;
            Zhi[idx] = hh;
            Zlo[idx] = __float2bfloat16(v - __bfloat162float(hh));
        }
    }
}

// ---------------------------------------------------------------------------
extern "C" void kernel_launch(void* const* d_in, const int* in_sizes, int n_in,
                              void* d_out, int out_size)
{
    const float* x      = (const float*)d_in[0];
    const float* w_attn = (const float*)d_in[1];
    const float* b_attn = (const float*)d_in[2];
    const float* w_proj = (const float*)d_in[3];
    const float* b_proj = (const float*)d_in[4];
    float* out = (float*)d_out;

    void *p;
    cudaGetSymbolAddress(&p, g_qkv); float* qkv = (float*)p;
    cudaGetSymbolAddress(&p, g_xh);  __nv_bfloat16* xh = (__nv_bfloat16*)p;
    cudaGetSymbolAddress(&p, g_xl);  __nv_bfloat16* xl = (__nv_bfloat16*)p;
    cudaGetSymbolAddress(&p, g_wah); __nv_bfloat16* wah = (__nv_bfloat16*)p;
    cudaGetSymbolAddress(&p, g_wal); __nv_bfloat16* wal = (__nv_bfloat16*)p;
    cudaGetSymbolAddress(&p, g_wph); __nv_bfloat16* wph = (__nv_bfloat16*)p;
    cudaGetSymbolAddress(&p, g_wpl); __nv_bfloat16* wpl = (__nv_bfloat16*)p;
    cudaGetSymbolAddress(&p, g_zh);  __nv_bfloat16* zh = (__nv_bfloat16*)p;
    cudaGetSymbolAddress(&p, g_zl);  __nv_bfloat16* zl = (__nv_bfloat16*)p;

    // 0) fp32 -> bf16 hi/lo splits
    split_f32<<<(T_DIM * C_DIM) / 1024, 256>>>(x, xh, xl, T_DIM * C_DIM);
    split_f32<<<(QKV_N * C_DIM) / 1024, 256>>>(w_attn, wah, wal, QKV_N * C_DIM);
    split_f32<<<(C_DIM * C_DIM) / 1024, 256>>>(w_proj, wph, wpl, C_DIM * C_DIM);

    constexpr int GEMM_SMEM = 2 * 4 * 128 * 144;   // 147456 B
    cudaFuncSetAttribute(gemm_mma_bf16x3,
                         cudaFuncAttributeMaxDynamicSharedMemorySize, GEMM_SMEM);

    // 1) QKV projection: (2048,3072) = x @ w_attn^T + b_attn
    {
        dim3 grid(QKV_N / 128, T_DIM / 128);
        gemm_mma_bf16x3<<<grid, 512, GEMM_SMEM>>>(xh, xl, wah, wal, b_attn, qkv,
                                                  T_DIM, QKV_N, C_DIM);
    }

    // 2) Causal attention, fused permute, emits bf16 hi/lo z
    {
        const int smem = 4 * 64 * 64 * sizeof(float);
        cudaFuncSetAttribute(attn_kernel,
                             cudaFuncAttributeMaxDynamicSharedMemorySize, smem);
        dim3 grid(T_DIM / 64, NHEAD);
        attn_kernel<<<grid, 256, smem>>>(qkv, zh, zl);
    }

    // 3) Output projection: (2048,1024) = Z @ w_proj^T + b_proj
    {
        dim3 grid(C_DIM / 128, T_DIM / 128);
        gemm_mma_bf16x3<<<grid, 512, GEMM_SMEM>>>(zh, zl, wph, wpl, b_proj, out,
                                                  T_DIM, C_DIM, C_DIM);
    }
}

// round 8
// speedup vs baseline: 2.5936x; 1.7600x over previous
#include <cuda_runtime.h>
#include <cuda_bf16.h>
#include <cstdint>

#define T_DIM 2048
#define C_DIM 1024
#define NHEAD 16
#define HDIM  64
#define QKV_N (3 * C_DIM)

// ---------------------------------------------------------------------------
// Scratch (__device__ globals; allocation-free rule)
// ---------------------------------------------------------------------------
__device__ __nv_bfloat16 g_qkvh[T_DIM * QKV_N], g_qkvl[T_DIM * QKV_N];
__device__ __nv_bfloat16 g_xh[T_DIM * C_DIM],  g_xl[T_DIM * C_DIM];
__device__ __nv_bfloat16 g_wah[QKV_N * C_DIM], g_wal[QKV_N * C_DIM];
__device__ __nv_bfloat16 g_wph[C_DIM * C_DIM], g_wpl[C_DIM * C_DIM];
__device__ __nv_bfloat16 g_zh[T_DIM * C_DIM],  g_zl[T_DIM * C_DIM];

// ---------------------------------------------------------------------------
// PTX helpers — sm_80-era only (harness stages PTX at compute_103)
// ---------------------------------------------------------------------------
__device__ __forceinline__ uint32_t smem_u32(const void* p) {
    uint32_t a;
    asm("{ .reg .u64 t; cvta.to.shared.u64 t, %1; cvt.u32.u64 %0, t; }"
        : "=r"(a) : "l"(p));
    return a;
}
__device__ __forceinline__ void cp_async16(uint32_t s, const void* g) {
    asm volatile("cp.async.cg.shared.global [%0], [%1], 16;" :: "r"(s), "l"(g));
}
#define CP_COMMIT() asm volatile("cp.async.commit_group;" ::: "memory")
#define CP_WAIT1()  asm volatile("cp.async.wait_group 1;" ::: "memory")
#define CP_WAIT0()  asm volatile("cp.async.wait_group 0;" ::: "memory")

#define LDM4(R, addr) \
    asm volatile("ldmatrix.sync.aligned.m8n8.x4.shared.b16 {%0,%1,%2,%3}, [%4];" \
        : "=r"((R)[0]), "=r"((R)[1]), "=r"((R)[2]), "=r"((R)[3]) : "r"(addr))
#define LDMT4(R, addr) \
    asm volatile("ldmatrix.sync.aligned.m8n8.x4.trans.shared.b16 {%0,%1,%2,%3}, [%4];" \
        : "=r"((R)[0]), "=r"((R)[1]), "=r"((R)[2]), "=r"((R)[3]) : "r"(addr))

#define MMA16816(c, a, b0, b1) \
    asm volatile("mma.sync.aligned.m16n8k16.row.col.f32.bf16.bf16.f32 " \
        "{%0,%1,%2,%3}, {%4,%5,%6,%7}, {%8,%9}, {%0,%1,%2,%3};" \
        : "+f"((c)[0]), "+f"((c)[1]), "+f"((c)[2]), "+f"((c)[3]) \
        : "r"((a)[0]), "r"((a)[1]), "r"((a)[2]), "r"((a)[3]), "r"(b0), "r"(b1))

__device__ __forceinline__ uint32_t pack_bf16x2(__nv_bfloat16 a, __nv_bfloat16 b) {
    uint16_t ua = *(uint16_t*)&a, ub = *(uint16_t*)&b;
    return (uint32_t)ua | ((uint32_t)ub << 16);
}
__device__ __forceinline__ void pack_hilo(float x, float y,
                                          uint32_t& hi, uint32_t& lo) {
    __nv_bfloat16 hx = __float2bfloat16(x);
    __nv_bfloat16 hy = __float2bfloat16(y);
    __nv_bfloat16 lx = __float2bfloat16(x - __bfloat162float(hx));
    __nv_bfloat16 ly = __float2bfloat16(y - __bfloat162float(hy));
    hi = pack_bf16x2(hx, hy);
    lo = pack_bf16x2(lx, ly);
}

// ---------------------------------------------------------------------------
// fp32 -> (hi, lo) bf16 split
// ---------------------------------------------------------------------------
__global__ __launch_bounds__(256) void split_f32(
    const float* __restrict__ src, __nv_bfloat16* __restrict__ hi,
    __nv_bfloat16* __restrict__ lo, int n)
{
    int i = (blockIdx.x * 256 + threadIdx.x) * 4;
    if (i >= n) return;
    float4 v = *(const float4*)(src + i);
    float vv[4] = {v.x, v.y, v.z, v.w};
    #pragma unroll
    for (int j = 0; j < 4; j++) {
        __nv_bfloat16 h = __float2bfloat16(vv[j]);
        hi[i + j] = h;
        lo[i + j] = __float2bfloat16(vv[j] - __bfloat162float(h));
    }
}

// ---------------------------------------------------------------------------
// mma.sync NT GEMM, bf16 3-pass split + bias.
// SPLIT_OUT=false: fp32 C. SPLIT_OUT=true: bf16 hi/lo pair outputs (Ch, Cl).
// ---------------------------------------------------------------------------
template <bool SPLIT_OUT>
__global__ __launch_bounds__(512, 1) void gemm_mma_bf16x3(
    const __nv_bfloat16* __restrict__ Ahi, const __nv_bfloat16* __restrict__ Alo,
    const __nv_bfloat16* __restrict__ Bhi, const __nv_bfloat16* __restrict__ Blo,
    const float* __restrict__ bias, float* __restrict__ C,
    __nv_bfloat16* __restrict__ Ch, __nv_bfloat16* __restrict__ Cl,
    int M, int N, int K)
{
    constexpr int PITCHB = 144;
    constexpr int MAT    = 128 * PITCHB;
    constexpr int OFF_AH = 0, OFF_AL = MAT, OFF_BH = 2 * MAT, OFF_BL = 3 * MAT;
    constexpr int STAGE  = 4 * MAT;

    extern __shared__ char smem[];
    const uint32_t base = smem_u32(smem);

    const int tid  = threadIdx.x;
    const int warp = tid >> 5, lane = tid & 31;
    const int wm = warp & 3, wn = warp >> 2;
    const int bm = blockIdx.y * 128, bn = blockIdx.x * 128;

    const uint32_t a_row = (uint32_t)(wm * 32 + ((lane >> 3) & 1) * 8 + (lane & 7));
    const uint32_t a_ko  = (uint32_t)((lane >> 4) * 8);
    const uint32_t b_row = (uint32_t)(wn * 32 + (lane >> 4) * 8 + (lane & 7));
    const uint32_t b_ko  = (uint32_t)(((lane >> 3) & 1) * 8);

    auto load_chunk = [&](int c) {
        const uint32_t st = base + (uint32_t)(c & 1) * STAGE;
        const int k0 = c * 64;
        #pragma unroll
        for (int j = 0; j < 2; j++) {
            int g = tid + 512 * j;
            int r = g >> 3, sg = g & 7;
            uint32_t so = (uint32_t)(r * PITCHB + sg * 16);
            size_t ga = (size_t)(bm + r) * K + k0 + sg * 8;
            size_t gb = (size_t)(bn + r) * K + k0 + sg * 8;
            cp_async16(st + OFF_AH + so, Ahi + ga);
            cp_async16(st + OFF_AL + so, Alo + ga);
            cp_async16(st + OFF_BH + so, Bhi + gb);
            cp_async16(st + OFF_BL + so, Blo + gb);
        }
        CP_COMMIT();
    };

    float acc[2][4][4];
    #pragma unroll
    for (int mi = 0; mi < 2; mi++)
        #pragma unroll
        for (int ni = 0; ni < 4; ni++)
            #pragma unroll
            for (int q = 0; q < 4; q++) acc[mi][ni][q] = 0.f;

    const int nch = K / 64;
    load_chunk(0);

    for (int c = 0; c < nch; c++) {
        if (c + 1 < nch) { load_chunk(c + 1); CP_WAIT1(); }
        else             { CP_WAIT0(); }
        __syncthreads();

        const uint32_t st = base + (uint32_t)(c & 1) * STAGE;
        #pragma unroll
        for (int ks = 0; ks < 4; ks++) {
            uint32_t Ah[2][4], Al[2][4], Bh[2][4], Bl[2][4];
            #pragma unroll
            for (int mi = 0; mi < 2; mi++) {
                uint32_t ao = (a_row + mi * 16) * PITCHB + (ks * 16 + a_ko) * 2;
                LDM4(Ah[mi], st + OFF_AH + ao);
                LDM4(Al[mi], st + OFF_AL + ao);
            }
            #pragma unroll
            for (int nt = 0; nt < 2; nt++) {
                uint32_t bo = (b_row + nt * 16) * PITCHB + (ks * 16 + b_ko) * 2;
                LDM4(Bh[nt], st + OFF_BH + bo);
                LDM4(Bl[nt], st + OFF_BL + bo);
            }
            #pragma unroll
            for (int mi = 0; mi < 2; mi++)
                #pragma unroll
                for (int ni = 0; ni < 4; ni++) {
                    const uint32_t bh0 = Bh[ni >> 1][(ni & 1) * 2];
                    const uint32_t bh1 = Bh[ni >> 1][(ni & 1) * 2 + 1];
                    const uint32_t bl0 = Bl[ni >> 1][(ni & 1) * 2];
                    const uint32_t bl1 = Bl[ni >> 1][(ni & 1) * 2 + 1];
                    MMA16816(acc[mi][ni], Ah[mi], bh0, bh1);
                    MMA16816(acc[mi][ni], Ah[mi], bl0, bl1);
                    MMA16816(acc[mi][ni], Al[mi], bh0, bh1);
                }
        }
        __syncthreads();
    }

    const int r0 = bm + wm * 32 + (lane >> 2);
    const int c0 = bn + wn * 32 + (lane & 3) * 2;
    #pragma unroll
    for (int mi = 0; mi < 2; mi++)
        #pragma unroll
        for (int ni = 0; ni < 4; ni++) {
            int row = r0 + mi * 16;
            int col = c0 + ni * 8;
            float2 b2 = *(const float2*)(bias + col);
            float v0 = acc[mi][ni][0] + b2.x, v1 = acc[mi][ni][1] + b2.y;
            float v2 = acc[mi][ni][2] + b2.x, v3 = acc[mi][ni][3] + b2.y;
            if (!SPLIT_OUT) {
                *(float2*)(C + (size_t)row * N + col)       = make_float2(v0, v1);
                *(float2*)(C + (size_t)(row + 8) * N + col) = make_float2(v2, v3);
            } else {
                uint32_t h0, l0, h1, l1;
                pack_hilo(v0, v1, h0, l0);
                pack_hilo(v2, v3, h1, l1);
                *(uint32_t*)(Ch + (size_t)row * N + col)       = h0;
                *(uint32_t*)(Cl + (size_t)row * N + col)       = l0;
                *(uint32_t*)(Ch + (size_t)(row + 8) * N + col) = h1;
                *(uint32_t*)(Cl + (size_t)(row + 8) * N + col) = l1;
            }
        }
}

// ---------------------------------------------------------------------------
// Tensor-core flash attention (bf16 hi/lo 3-pass, fp32 softmax).
// Block = (head, 128-query tile), 8 warps; warp w owns rows w*16..w*16+15 and
// all 128 keys -> softmax stats stay within the warp (shfl over 4 lanes/row).
// Emits z hi/lo into the bug-faithful layout:
//   Z[h*128 + 2*d + (t>>10)][t & 1023] = y[h][t][d]
// ---------------------------------------------------------------------------
__global__ __launch_bounds__(256, 1) void attn_mma(
    const __nv_bfloat16* __restrict__ qkvh, const __nv_bfloat16* __restrict__ qkvl,
    __nv_bfloat16* __restrict__ Zhi, __nv_bfloat16* __restrict__ Zlo)
{
    constexpr int PITCH = 144;
    constexpr int MAT   = 128 * PITCH;          // 18432
    constexpr int QH_OFF = 0, QL_OFF = MAT;
    constexpr int ST0 = 2 * MAT;                // 36864
    constexpr int KH = 0, KL = MAT, VH = 2 * MAT, VL = 3 * MAT;
    constexpr int STAGE = 4 * MAT;              // 73728

    extern __shared__ char smem[];
    const uint32_t base = smem_u32(smem);

    const int tid  = threadIdx.x;
    const int warp = tid >> 5, lane = tid & 31;
    const int wq   = warp * 16;
    const int qi   = 15 - (int)blockIdx.x;      // heavy tiles first
    const int h    = blockIdx.y;

    const uint32_t a_rl = (uint32_t)(((lane >> 3) & 1) * 8 + (lane & 7));
    const uint32_t a_ko = (uint32_t)((lane >> 4) * 8);
    const uint32_t b_rl = (uint32_t)((lane >> 4) * 8 + (lane & 7));
    const uint32_t b_ko = (uint32_t)(((lane >> 3) & 1) * 8);

    // --- load Q tile (hi+lo): 128 rows x 64 bf16 each
    {
        #pragma unroll
        for (int j = 0; j < 4; j++) {
            int g = tid + 256 * j;
            int r = g >> 3, sg = g & 7;
            uint32_t so = (uint32_t)(r * PITCH + sg * 16);
            size_t ga = (size_t)(qi * 128 + r) * QKV_N + h * HDIM + sg * 8;
            cp_async16(base + QH_OFF + so, qkvh + ga);
            cp_async16(base + QL_OFF + so, qkvl + ga);
        }
    }
    auto load_kv = [&](int kt) {
        const uint32_t st = base + ST0 + (uint32_t)(kt & 1) * STAGE;
        #pragma unroll
        for (int j = 0; j < 4; j++) {
            int g = tid + 256 * j;
            int r = g >> 3, sg = g & 7;
            uint32_t so = (uint32_t)(r * PITCH + sg * 16);
            size_t gk = (size_t)(kt * 128 + r) * QKV_N + C_DIM     + h * HDIM + sg * 8;
            size_t gv = (size_t)(kt * 128 + r) * QKV_N + 2 * C_DIM + h * HDIM + sg * 8;
            cp_async16(st + KH + so, qkvh + gk);
            cp_async16(st + KL + so, qkvl + gk);
            cp_async16(st + VH + so, qkvh + gv);
            cp_async16(st + VL + so, qkvl + gv);
        }
    };
    load_kv(0);
    CP_COMMIT();

    float m_run[2] = {-1e30f, -1e30f};
    float l_run[2] = {0.f, 0.f};
    float O[8][4];
    #pragma unroll
    for (int a = 0; a < 8; a++)
        #pragma unroll
        for (int q = 0; q < 4; q++) O[a][q] = 0.f;

    for (int kt = 0; kt <= qi; kt++) {
        __syncthreads();                       // protect buffer (kt+1)&1
        if (kt + 1 <= qi) { load_kv(kt + 1); CP_COMMIT(); CP_WAIT1(); }
        else              { CP_WAIT0(); }
        __syncthreads();

        const uint32_t sk = base + ST0 + (uint32_t)(kt & 1) * STAGE;

        // ---- S = Q K^T (3-pass), fp32 accum: 16 n8-atoms over 128 keys
        float S[16][4];
        #pragma unroll
        for (int a = 0; a < 16; a++)
            #pragma unroll
            for (int q = 0; q < 4; q++) S[a][q] = 0.f;

        #pragma unroll
        for (int ks = 0; ks < 4; ks++) {
            uint32_t Ah[4], Al[4];
            uint32_t ao = (wq + a_rl) * PITCH + (ks * 16 + a_ko) * 2;
            LDM4(Ah, base + QH_OFF + ao);
            LDM4(Al, base + QL_OFF + ao);
            #pragma unroll
            for (int ng = 0; ng < 8; ng++) {
                uint32_t Bh[4], Bl[4];
                uint32_t bo = (ng * 16 + b_rl) * PITCH + (ks * 16 + b_ko) * 2;
                LDM4(Bh, sk + KH + bo);
                LDM4(Bl, sk + KL + bo);
                MMA16816(S[2*ng],   Ah, Bh[0], Bh[1]);
                MMA16816(S[2*ng+1], Ah, Bh[2], Bh[3]);
                MMA16816(S[2*ng],   Ah, Bl[0], Bl[1]);
                MMA16816(S[2*ng+1], Ah, Bl[2], Bl[3]);
                MMA16816(S[2*ng],   Al, Bh[0], Bh[1]);
                MMA16816(S[2*ng+1], Al, Bh[2], Bh[3]);
            }
        }
        #pragma unroll
        for (int a = 0; a < 16; a++)
            #pragma unroll
            for (int q = 0; q < 4; q++) S[a][q] *= 0.125f;

        if (kt == qi) {   // diagonal tile: causal mask
            int rbase = qi * 128 + wq + (lane >> 2);
            int cbase = kt * 128 + (lane & 3) * 2;
            #pragma unroll
            for (int a = 0; a < 16; a++)
                #pragma unroll
                for (int q = 0; q < 4; q++) {
                    int row = rbase + (q >= 2 ? 8 : 0);
                    int col = cbase + a * 8 + (q & 1);
                    if (col > row) S[a][q] = -1e30f;
                }
        }

        // ---- online softmax (per thread: 2 rows)
        #pragma unroll
        for (int i = 0; i < 2; i++) {
            float mx = -1e30f;
            #pragma unroll
            for (int a = 0; a < 16; a++)
                mx = fmaxf(mx, fmaxf(S[a][2*i], S[a][2*i+1]));
            mx = fmaxf(mx, __shfl_xor_sync(0xffffffffu, mx, 1));
            mx = fmaxf(mx, __shfl_xor_sync(0xffffffffu, mx, 2));
            float mn = fmaxf(m_run[i], mx);
            float alpha = __expf(m_run[i] - mn);
            float sum = 0.f;
            #pragma unroll
            for (int a = 0; a < 16; a++) {
                float p0 = __expf(S[a][2*i]   - mn);
                float p1 = __expf(S[a][2*i+1] - mn);
                S[a][2*i] = p0; S[a][2*i+1] = p1;
                sum += p0 + p1;
            }
            sum += __shfl_xor_sync(0xffffffffu, sum, 1);
            sum += __shfl_xor_sync(0xffffffffu, sum, 2);
            l_run[i] = l_run[i] * alpha + sum;
            m_run[i] = mn;
            #pragma unroll
            for (int a = 0; a < 8; a++) {
                O[a][2*i]   *= alpha;
                O[a][2*i+1] *= alpha;
            }
        }

        // ---- P -> A-fragments (hi/lo), register-only repack
        uint32_t Ph[8][4], Pl[8][4];
        #pragma unroll
        for (int kc = 0; kc < 8; kc++) {
            pack_hilo(S[2*kc][0],   S[2*kc][1],   Ph[kc][0], Pl[kc][0]);
            pack_hilo(S[2*kc][2],   S[2*kc][3],   Ph[kc][1], Pl[kc][1]);
            pack_hilo(S[2*kc+1][0], S[2*kc+1][1], Ph[kc][2], Pl[kc][2]);
            pack_hilo(S[2*kc+1][2], S[2*kc+1][3], Ph[kc][3], Pl[kc][3]);
        }

        // ---- O += P V (3-pass); V via ldmatrix.trans from (key, d) rows
        #pragma unroll
        for (int kc = 0; kc < 8; kc++) {
            uint32_t krow = (uint32_t)(kc * 16) + a_rl;
            #pragma unroll
            for (int dg = 0; dg < 4; dg++) {
                uint32_t Vh4[4], Vl4[4];
                uint32_t vo = krow * PITCH + (dg * 16 + a_ko) * 2;
                LDMT4(Vh4, sk + VH + vo);
                LDMT4(Vl4, sk + VL + vo);
                MMA16816(O[2*dg],   Ph[kc], Vh4[0], Vh4[1]);
                MMA16816(O[2*dg+1], Ph[kc], Vh4[2], Vh4[3]);
                MMA16816(O[2*dg],   Ph[kc], Vl4[0], Vl4[1]);
                MMA16816(O[2*dg+1], Ph[kc], Vl4[2], Vl4[3]);
                MMA16816(O[2*dg],   Pl[kc], Vh4[0], Vh4[1]);
                MMA16816(O[2*dg+1], Pl[kc], Vh4[2], Vh4[3]);
            }
        }
    }

    // ---- epilogue: normalize, split hi/lo, scatter into bug-faithful layout
    #pragma unroll
    for (int i = 0; i < 2; i++) {
        float inv = 1.0f / l_run[i];
        int t   = qi * 128 + wq + (lane >> 2) + 8 * i;
        int col = t & (C_DIM - 1);
        int thi = t >> 10;
        #pragma unroll
        for (int a = 0; a < 8; a++)
            #pragma unroll
            for (int q = 0; q < 2; q++) {
                int d = a * 8 + (lane & 3) * 2 + q;
                float v = O[a][2*i + q] * inv;
                __nv_bfloat16 hh = __float2bfloat16(v);
                int row = h * 128 + 2 * d + thi;
                size_t idx = (size_t)row * C_DIM + col;
                Zhi[idx] = hh;
                Zlo[idx] = __float2bfloat16(v - __bfloat162float(hh));
            }
    }
}

// ---------------------------------------------------------------------------
extern "C" void kernel_launch(void* const* d_in, const int* in_sizes, int n_in,
                              void* d_out, int out_size)
{
    const float* x      = (const float*)d_in[0];
    const float* w_attn = (const float*)d_in[1];
    const float* b_attn = (const float*)d_in[2];
    const float* w_proj = (const float*)d_in[3];
    const float* b_proj = (const float*)d_in[4];
    float* out = (float*)d_out;

    void *p;
    cudaGetSymbolAddress(&p, g_qkvh); __nv_bfloat16* qh = (__nv_bfloat16*)p;
    cudaGetSymbolAddress(&p, g_qkvl); __nv_bfloat16* ql = (__nv_bfloat16*)p;
    cudaGetSymbolAddress(&p, g_xh);   __nv_bfloat16* xh = (__nv_bfloat16*)p;
    cudaGetSymbolAddress(&p, g_xl);   __nv_bfloat16* xl = (__nv_bfloat16*)p;
    cudaGetSymbolAddress(&p, g_wah);  __nv_bfloat16* wah = (__nv_bfloat16*)p;
    cudaGetSymbolAddress(&p, g_wal);  __nv_bfloat16* wal = (__nv_bfloat16*)p;
    cudaGetSymbolAddress(&p, g_wph);  __nv_bfloat16* wph = (__nv_bfloat16*)p;
    cudaGetSymbolAddress(&p, g_wpl);  __nv_bfloat16* wpl = (__nv_bfloat16*)p;
    cudaGetSymbolAddress(&p, g_zh);   __nv_bfloat16* zh = (__nv_bfloat16*)p;
    cudaGetSymbolAddress(&p, g_zl);   __nv_bfloat16* zl = (__nv_bfloat16*)p;

    // 0) fp32 -> bf16 hi/lo splits
    split_f32<<<(T_DIM * C_DIM) / 1024, 256>>>(x, xh, xl, T_DIM * C_DIM);
    split_f32<<<(QKV_N * C_DIM) / 1024, 256>>>(w_attn, wah, wal, QKV_N * C_DIM);
    split_f32<<<(C_DIM * C_DIM) / 1024, 256>>>(w_proj, wph, wpl, C_DIM * C_DIM);

    constexpr int GEMM_SMEM = 2 * 4 * 128 * 144;   // 147456 B
    cudaFuncSetAttribute(gemm_mma_bf16x3<true>,
                         cudaFuncAttributeMaxDynamicSharedMemorySize, GEMM_SMEM);
    cudaFuncSetAttribute(gemm_mma_bf16x3<false>,
                         cudaFuncAttributeMaxDynamicSharedMemorySize, GEMM_SMEM);

    // 1) QKV projection -> bf16 hi/lo qkv
    {
        dim3 grid(QKV_N / 128, T_DIM / 128);
        gemm_mma_bf16x3<true><<<grid, 512, GEMM_SMEM>>>(
            xh, xl, wah, wal, b_attn, nullptr, qh, ql, T_DIM, QKV_N, C_DIM);
    }

    // 2) Tensor-core flash attention, fused permute, emits bf16 hi/lo z
    {
        constexpr int ATTN_SMEM = (2 + 8) * 128 * 144;   // 184320 B
        cudaFuncSetAttribute(attn_mma,
                             cudaFuncAttributeMaxDynamicSharedMemorySize, ATTN_SMEM);
        dim3 grid(T_DIM / 128, NHEAD);
        attn_mma<<<grid, 256, ATTN_SMEM>>>(qh, ql, zh, zl);
    }

    // 3) Output projection: (2048,1024) = Z @ w_proj^T + b_proj (fp32 out)
    {
        dim3 grid(C_DIM / 128, T_DIM / 128);
        gemm_mma_bf16x3<false><<<grid, 512, GEMM_SMEM>>>(
            zh, zl, wph, wpl, b_proj, out, nullptr, nullptr, T_DIM, C_DIM, C_DIM);
    }
}

// round 9
// speedup vs baseline: 2.9294x; 1.1295x over previous
#include <cuda_runtime.h>
#include <cuda_bf16.h>
#include <cstdint>

#define T_DIM 2048
#define C_DIM 1024
#define NHEAD 16
#define HDIM  64
#define QKV_N (3 * C_DIM)

// ---------------------------------------------------------------------------
// Scratch (__device__ globals; allocation-free rule)
// ---------------------------------------------------------------------------
__device__ __nv_bfloat16 g_qkvh[T_DIM * QKV_N], g_qkvl[T_DIM * QKV_N];
__device__ __nv_bfloat16 g_xh[T_DIM * C_DIM],  g_xl[T_DIM * C_DIM];
__device__ __nv_bfloat16 g_wah[QKV_N * C_DIM], g_wal[QKV_N * C_DIM];
__device__ __nv_bfloat16 g_wph[C_DIM * C_DIM], g_wpl[C_DIM * C_DIM];
__device__ __nv_bfloat16 g_zh[T_DIM * C_DIM],  g_zl[T_DIM * C_DIM];

// ---------------------------------------------------------------------------
// PTX helpers — sm_80-era only (harness stages PTX at compute_103)
// ---------------------------------------------------------------------------
__device__ __forceinline__ uint32_t smem_u32(const void* p) {
    uint32_t a;
    asm("{ .reg .u64 t; cvta.to.shared.u64 t, %1; cvt.u32.u64 %0, t; }"
        : "=r"(a) : "l"(p));
    return a;
}
__device__ __forceinline__ void cp_async16(uint32_t s, const void* g) {
    asm volatile("cp.async.cg.shared.global [%0], [%1], 16;" :: "r"(s), "l"(g));
}
#define CP_COMMIT() asm volatile("cp.async.commit_group;" ::: "memory")
#define CP_WAIT1()  asm volatile("cp.async.wait_group 1;" ::: "memory")
#define CP_WAIT0()  asm volatile("cp.async.wait_group 0;" ::: "memory")

#define LDM4(R, addr) \
    asm volatile("ldmatrix.sync.aligned.m8n8.x4.shared.b16 {%0,%1,%2,%3}, [%4];" \
        : "=r"((R)[0]), "=r"((R)[1]), "=r"((R)[2]), "=r"((R)[3]) : "r"(addr))
#define LDMT4(R, addr) \
    asm volatile("ldmatrix.sync.aligned.m8n8.x4.trans.shared.b16 {%0,%1,%2,%3}, [%4];" \
        : "=r"((R)[0]), "=r"((R)[1]), "=r"((R)[2]), "=r"((R)[3]) : "r"(addr))

#define MMA16816(c, a, b0, b1) \
    asm volatile("mma.sync.aligned.m16n8k16.row.col.f32.bf16.bf16.f32 " \
        "{%0,%1,%2,%3}, {%4,%5,%6,%7}, {%8,%9}, {%0,%1,%2,%3};" \
        : "+f"((c)[0]), "+f"((c)[1]), "+f"((c)[2]), "+f"((c)[3]) \
        : "r"((a)[0]), "r"((a)[1]), "r"((a)[2]), "r"((a)[3]), "r"(b0), "r"(b1))

__device__ __forceinline__ uint32_t pack_bf16x2(__nv_bfloat16 a, __nv_bfloat16 b) {
    uint16_t ua = *(uint16_t*)&a, ub = *(uint16_t*)&b;
    return (uint32_t)ua | ((uint32_t)ub << 16);
}
__device__ __forceinline__ void pack_hilo(float x, float y,
                                          uint32_t& hi, uint32_t& lo) {
    __nv_bfloat16 hx = __float2bfloat16(x);
    __nv_bfloat16 hy = __float2bfloat16(y);
    __nv_bfloat16 lx = __float2bfloat16(x - __bfloat162float(hx));
    __nv_bfloat16 ly = __float2bfloat16(y - __bfloat162float(hy));
    hi = pack_bf16x2(hx, hy);
    lo = pack_bf16x2(lx, ly);
}

// ---------------------------------------------------------------------------
// fp32 -> (hi, lo) bf16 split
// ---------------------------------------------------------------------------
__global__ __launch_bounds__(256) void split_f32(
    const float* __restrict__ src, __nv_bfloat16* __restrict__ hi,
    __nv_bfloat16* __restrict__ lo, int n)
{
    int i = (blockIdx.x * 256 + threadIdx.x) * 4;
    if (i >= n) return;
    float4 v = *(const float4*)(src + i);
    float vv[4] = {v.x, v.y, v.z, v.w};
    #pragma unroll
    for (int j = 0; j < 4; j++) {
        __nv_bfloat16 h = __float2bfloat16(vv[j]);
        hi[i + j] = h;
        lo[i + j] = __float2bfloat16(vv[j] - __bfloat162float(h));
    }
}

// ---------------------------------------------------------------------------
// mma.sync NT GEMM, bf16 3-pass split + bias.
// 128x64 CTA tile, 256 threads (8 warps = 4x2 of 32x32 warp tiles),
// 2 CTAs/SM (smem 110.6KB, regs within 64K/SM budget for 512 threads).
// SPLIT_OUT=false: fp32 C. SPLIT_OUT=true: bf16 hi/lo pair outputs (Ch, Cl).
// ---------------------------------------------------------------------------
template <bool SPLIT_OUT>
__global__ __launch_bounds__(256, 2) void gemm_mma_bf16x3(
    const __nv_bfloat16* __restrict__ Ahi, const __nv_bfloat16* __restrict__ Alo,
    const __nv_bfloat16* __restrict__ Bhi, const __nv_bfloat16* __restrict__ Blo,
    const float* __restrict__ bias, float* __restrict__ C,
    __nv_bfloat16* __restrict__ Ch, __nv_bfloat16* __restrict__ Cl,
    int M, int N, int K)
{
    constexpr int PITCHB = 144;
    constexpr int A_MAT  = 128 * PITCHB;      // 18432
    constexpr int B_MAT  = 64 * PITCHB;       // 9216
    constexpr int OFF_AH = 0, OFF_AL = A_MAT;
    constexpr int OFF_BH = 2 * A_MAT, OFF_BL = 2 * A_MAT + B_MAT;
    constexpr int STAGE  = 2 * A_MAT + 2 * B_MAT;   // 55296

    extern __shared__ char smem[];
    const uint32_t base = smem_u32(smem);

    const int tid  = threadIdx.x;
    const int warp = tid >> 5, lane = tid & 31;
    const int wm = warp & 3, wn = warp >> 2;         // 4 x 2 warps
    const int bm = blockIdx.y * 128, bn = blockIdx.x * 64;

    const uint32_t a_row = (uint32_t)(wm * 32 + ((lane >> 3) & 1) * 8 + (lane & 7));
    const uint32_t a_ko  = (uint32_t)((lane >> 4) * 8);
    const uint32_t b_row = (uint32_t)(wn * 32 + (lane >> 4) * 8 + (lane & 7));
    const uint32_t b_ko  = (uint32_t)(((lane >> 3) & 1) * 8);

    auto load_chunk = [&](int c) {
        const uint32_t st = base + (uint32_t)(c & 1) * STAGE;
        const int k0 = c * 64;
        #pragma unroll
        for (int j = 0; j < 4; j++) {                 // A: 1024 segs x 2 mats
            int g = tid + 256 * j;
            int r = g >> 3, sg = g & 7;
            uint32_t so = (uint32_t)(r * PITCHB + sg * 16);
            size_t ga = (size_t)(bm + r) * K + k0 + sg * 8;
            cp_async16(st + OFF_AH + so, Ahi + ga);
            cp_async16(st + OFF_AL + so, Alo + ga);
        }
        #pragma unroll
        for (int j = 0; j < 2; j++) {                 // B: 512 segs x 2 mats
            int g = tid + 256 * j;
            int r = g >> 3, sg = g & 7;
            uint32_t so = (uint32_t)(r * PITCHB + sg * 16);
            size_t gb = (size_t)(bn + r) * K + k0 + sg * 8;
            cp_async16(st + OFF_BH + so, Bhi + gb);
            cp_async16(st + OFF_BL + so, Blo + gb);
        }
        CP_COMMIT();
    };

    float acc[2][4][4];
    #pragma unroll
    for (int mi = 0; mi < 2; mi++)
        #pragma unroll
        for (int ni = 0; ni < 4; ni++)
            #pragma unroll
            for (int q = 0; q < 4; q++) acc[mi][ni][q] = 0.f;

    const int nch = K / 64;
    load_chunk(0);

    for (int c = 0; c < nch; c++) {
        if (c + 1 < nch) { load_chunk(c + 1); CP_WAIT1(); }
        else             { CP_WAIT0(); }
        __syncthreads();

        const uint32_t st = base + (uint32_t)(c & 1) * STAGE;
        #pragma unroll
        for (int ks = 0; ks < 4; ks++) {
            uint32_t Ah[2][4], Al[2][4], Bh[2][4], Bl[2][4];
            #pragma unroll
            for (int mi = 0; mi < 2; mi++) {
                uint32_t ao = (a_row + mi * 16) * PITCHB + (ks * 16 + a_ko) * 2;
                LDM4(Ah[mi], st + OFF_AH + ao);
                LDM4(Al[mi], st + OFF_AL + ao);
            }
            #pragma unroll
            for (int nt = 0; nt < 2; nt++) {
                uint32_t bo = (b_row + nt * 16) * PITCHB + (ks * 16 + b_ko) * 2;
                LDM4(Bh[nt], st + OFF_BH + bo);
                LDM4(Bl[nt], st + OFF_BL + bo);
            }
            #pragma unroll
            for (int mi = 0; mi < 2; mi++)
                #pragma unroll
                for (int ni = 0; ni < 4; ni++) {
                    const uint32_t bh0 = Bh[ni >> 1][(ni & 1) * 2];
                    const uint32_t bh1 = Bh[ni >> 1][(ni & 1) * 2 + 1];
                    const uint32_t bl0 = Bl[ni >> 1][(ni & 1) * 2];
                    const uint32_t bl1 = Bl[ni >> 1][(ni & 1) * 2 + 1];
                    MMA16816(acc[mi][ni], Ah[mi], bh0, bh1);
                    MMA16816(acc[mi][ni], Ah[mi], bl0, bl1);
                    MMA16816(acc[mi][ni], Al[mi], bh0, bh1);
                }
        }
        __syncthreads();
    }

    const int r0 = bm + wm * 32 + (lane >> 2);
    const int c0 = bn + wn * 32 + (lane & 3) * 2;
    #pragma unroll
    for (int mi = 0; mi < 2; mi++)
        #pragma unroll
        for (int ni = 0; ni < 4; ni++) {
            int row = r0 + mi * 16;
            int col = c0 + ni * 8;
            float2 b2 = *(const float2*)(bias + col);
            float v0 = acc[mi][ni][0] + b2.x, v1 = acc[mi][ni][1] + b2.y;
            float v2 = acc[mi][ni][2] + b2.x, v3 = acc[mi][ni][3] + b2.y;
            if (!SPLIT_OUT) {
                *(float2*)(C + (size_t)row * N + col)       = make_float2(v0, v1);
                *(float2*)(C + (size_t)(row + 8) * N + col) = make_float2(v2, v3);
            } else {
                uint32_t h0, l0, h1, l1;
                pack_hilo(v0, v1, h0, l0);
                pack_hilo(v2, v3, h1, l1);
                *(uint32_t*)(Ch + (size_t)row * N + col)       = h0;
                *(uint32_t*)(Cl + (size_t)row * N + col)       = l0;
                *(uint32_t*)(Ch + (size_t)(row + 8) * N + col) = h1;
                *(uint32_t*)(Cl + (size_t)(row + 8) * N + col) = l1;
            }
        }
}

// ---------------------------------------------------------------------------
// Tensor-core flash attention, split-key warp groups + paired q-tiles.
// 128 CTAs of UNIFORM work: CTA b handles q-tiles {15-b, b} (17 key-tiles
// total each). 512 threads = 2 key-groups x 8 warps; group g covers keys
// [g*64, g*64+64) of each staged 128-key tile with private online-softmax,
// merged through smem at the end of each q-tile.
// Emits z hi/lo into the bug-faithful layout:
//   Z[h*128 + 2*d + (t>>10)][t & 1023] = y[h][t][d]
// ---------------------------------------------------------------------------
__global__ __launch_bounds__(512, 1) void attn_mma(
    const __nv_bfloat16* __restrict__ qkvh, const __nv_bfloat16* __restrict__ qkvl,
    __nv_bfloat16* __restrict__ Zhi, __nv_bfloat16* __restrict__ Zlo)
{
    constexpr int PITCH = 144;
    constexpr int MAT   = 128 * PITCH;          // 18432
    constexpr int QH_OFF = 0, QL_OFF = MAT;
    constexpr int ST0 = 2 * MAT;                // 36864
    constexpr int KH = 0, KL = MAT, VH = 2 * MAT, VL = 3 * MAT;
    constexpr int STAGE = 4 * MAT;              // 73728

    extern __shared__ char smem[];
    const uint32_t base = smem_u32(smem);
    float* mergebuf = (float*)smem;

    const int tid  = threadIdx.x;
    const int warp = tid >> 5, lane = tid & 31;
    const int grp  = warp >> 3;                 // key group 0/1
    const int wg   = warp & 7;
    const int wq   = wg * 16;
    const int kh   = grp * 64;                  // key offset within tile
    const int h    = blockIdx.y;

    const float NEG_INF = __int_as_float(0xff800000);

    const uint32_t a_rl = (uint32_t)(((lane >> 3) & 1) * 8 + (lane & 7));
    const uint32_t a_ko = (uint32_t)((lane >> 4) * 8);
    const uint32_t b_rl = (uint32_t)((lane >> 4) * 8 + (lane & 7));
    const uint32_t b_ko = (uint32_t)(((lane >> 3) & 1) * 8);

    for (int pass = 0; pass < 2; pass++) {
        const int qi = pass == 0 ? (15 - (int)blockIdx.x) : (int)blockIdx.x;

        __syncthreads();   // previous pass fully done with smem

        // --- load Q tile (hi+lo): 1024 segs per matrix
        #pragma unroll
        for (int j = 0; j < 2; j++) {
            int g = tid + 512 * j;
            int r = g >> 3, sg = g & 7;
            uint32_t so = (uint32_t)(r * PITCH + sg * 16);
            size_t ga = (size_t)(qi * 128 + r) * QKV_N + h * HDIM + sg * 8;
            cp_async16(base + QH_OFF + so, qkvh + ga);
            cp_async16(base + QL_OFF + so, qkvl + ga);
        }
        auto load_kv = [&](int kt) {
            const uint32_t st = base + ST0 + (uint32_t)(kt & 1) * STAGE;
            #pragma unroll
            for (int j = 0; j < 2; j++) {
                int g = tid + 512 * j;
                int r = g >> 3, sg = g & 7;
                uint32_t so = (uint32_t)(r * PITCH + sg * 16);
                size_t gk = (size_t)(kt * 128 + r) * QKV_N + C_DIM     + h * HDIM + sg * 8;
                size_t gv = (size_t)(kt * 128 + r) * QKV_N + 2 * C_DIM + h * HDIM + sg * 8;
                cp_async16(st + KH + so, qkvh + gk);
                cp_async16(st + KL + so, qkvl + gk);
                cp_async16(st + VH + so, qkvh + gv);
                cp_async16(st + VL + so, qkvl + gv);
            }
        };
        load_kv(0);
        CP_COMMIT();

        float m_run[2] = {-1e30f, -1e30f};
        float l_run[2] = {0.f, 0.f};
        float O[8][4];
        #pragma unroll
        for (int a = 0; a < 8; a++)
            #pragma unroll
            for (int q = 0; q < 4; q++) O[a][q] = 0.f;

        for (int kt = 0; kt <= qi; kt++) {
            __syncthreads();
            if (kt + 1 <= qi) { load_kv(kt + 1); CP_COMMIT(); CP_WAIT1(); }
            else              { CP_WAIT0(); }
            __syncthreads();

            const uint32_t sk = base + ST0 + (uint32_t)(kt & 1) * STAGE;

            // ---- S = Q K^T for this group's 64 keys (3-pass), fp32 accum
            float S[8][4];
            #pragma unroll
            for (int a = 0; a < 8; a++)
                #pragma unroll
                for (int q = 0; q < 4; q++) S[a][q] = 0.f;

            #pragma unroll
            for (int ks = 0; ks < 4; ks++) {
                uint32_t Ah[4], Al[4];
                uint32_t ao = (wq + a_rl) * PITCH + (ks * 16 + a_ko) * 2;
                LDM4(Ah, base + QH_OFF + ao);
                LDM4(Al, base + QL_OFF + ao);
                #pragma unroll
                for (int ng = 0; ng < 4; ng++) {
                    uint32_t Bh[4], Bl[4];
                    uint32_t bo = (kh + ng * 16 + b_rl) * PITCH + (ks * 16 + b_ko) * 2;
                    LDM4(Bh, sk + KH + bo);
                    LDM4(Bl, sk + KL + bo);
                    MMA16816(S[2*ng],   Ah, Bh[0], Bh[1]);
                    MMA16816(S[2*ng+1], Ah, Bh[2], Bh[3]);
                    MMA16816(S[2*ng],   Ah, Bl[0], Bl[1]);
                    MMA16816(S[2*ng+1], Ah, Bl[2], Bl[3]);
                    MMA16816(S[2*ng],   Al, Bh[0], Bh[1]);
                    MMA16816(S[2*ng+1], Al, Bh[2], Bh[3]);
                }
            }
            #pragma unroll
            for (int a = 0; a < 8; a++)
                #pragma unroll
                for (int q = 0; q < 4; q++) S[a][q] *= 0.125f;

            if (kt == qi) {   // diagonal tile: causal mask (-INF so exp -> 0)
                int rbase = qi * 128 + wq + (lane >> 2);
                int cbase = kt * 128 + kh + (lane & 3) * 2;
                #pragma unroll
                for (int a = 0; a < 8; a++)
                    #pragma unroll
                    for (int q = 0; q < 4; q++) {
                        int row = rbase + (q >= 2 ? 8 : 0);
                        int col = cbase + a * 8 + (q & 1);
                        if (col > row) S[a][q] = NEG_INF;
                    }
            }

            // ---- online softmax (per thread: 2 rows; stats over 4 lanes/row)
            #pragma unroll
            for (int i = 0; i < 2; i++) {
                float mx = NEG_INF;
                #pragma unroll
                for (int a = 0; a < 8; a++)
                    mx = fmaxf(mx, fmaxf(S[a][2*i], S[a][2*i+1]));
                mx = fmaxf(mx, __shfl_xor_sync(0xffffffffu, mx, 1));
                mx = fmaxf(mx, __shfl_xor_sync(0xffffffffu, mx, 2));
                float mn = fmaxf(m_run[i], mx);    // >= -1e30, finite
                float alpha = __expf(m_run[i] - mn);
                float sum = 0.f;
                #pragma unroll
                for (int a = 0; a < 8; a++) {
                    float p0 = __expf(S[a][2*i]   - mn);
                    float p1 = __expf(S[a][2*i+1] - mn);
                    S[a][2*i] = p0; S[a][2*i+1] = p1;
                    sum += p0 + p1;
                }
                sum += __shfl_xor_sync(0xffffffffu, sum, 1);
                sum += __shfl_xor_sync(0xffffffffu, sum, 2);
                l_run[i] = l_run[i] * alpha + sum;
                m_run[i] = mn;
                #pragma unroll
                for (int a = 0; a < 8; a++) {
                    O[a][2*i]   *= alpha;
                    O[a][2*i+1] *= alpha;
                }
            }

            // ---- P -> A-fragments (hi/lo), register-only repack
            uint32_t Ph[4][4], Pl[4][4];
            #pragma unroll
            for (int kc = 0; kc < 4; kc++) {
                pack_hilo(S[2*kc][0],   S[2*kc][1],   Ph[kc][0], Pl[kc][0]);
                pack_hilo(S[2*kc][2],   S[2*kc][3],   Ph[kc][1], Pl[kc][1]);
                pack_hilo(S[2*kc+1][0], S[2*kc+1][1], Ph[kc][2], Pl[kc][2]);
                pack_hilo(S[2*kc+1][2], S[2*kc+1][3], Ph[kc][3], Pl[kc][3]);
            }

            // ---- O += P V over this group's 64 keys (3-pass)
            #pragma unroll
            for (int kc = 0; kc < 4; kc++) {
                uint32_t krow = (uint32_t)(kh + kc * 16) + a_rl;
                #pragma unroll
                for (int dg = 0; dg < 4; dg++) {
                    uint32_t Vh4[4], Vl4[4];
                    uint32_t vo = krow * PITCH + (dg * 16 + a_ko) * 2;
                    LDMT4(Vh4, sk + VH + vo);
                    LDMT4(Vl4, sk + VL + vo);
                    MMA16816(O[2*dg],   Ph[kc], Vh4[0], Vh4[1]);
                    MMA16816(O[2*dg+1], Ph[kc], Vh4[2], Vh4[3]);
                    MMA16816(O[2*dg],   Ph[kc], Vl4[0], Vl4[1]);
                    MMA16816(O[2*dg+1], Ph[kc], Vl4[2], Vl4[3]);
                    MMA16816(O[2*dg],   Pl[kc], Vh4[0], Vh4[1]);
                    MMA16816(O[2*dg+1], Pl[kc], Vh4[2], Vh4[3]);
                }
            }
        }

        // ---- cross-group merge via smem, then epilogue from group 0
        __syncthreads();
        const int slot = wg * 32 + lane;        // same (rows, cols) both groups
        float* buf = mergebuf + slot * 37;
        if (grp == 1) {
            buf[0] = m_run[0]; buf[1] = m_run[1];
            buf[2] = l_run[0]; buf[3] = l_run[1];
            #pragma unroll
            for (int a = 0; a < 8; a++)
                #pragma unroll
                for (int q = 0; q < 4; q++) buf[4 + a * 4 + q] = O[a][q];
        }
        __syncthreads();
        if (grp == 0) {
            #pragma unroll
            for (int i = 0; i < 2; i++) {
                float m1 = buf[i], l1 = buf[2 + i];
                float m = fmaxf(m_run[i], m1);
                float a0 = __expf(m_run[i] - m);
                float a1 = __expf(m1 - m);
                l_run[i] = l_run[i] * a0 + l1 * a1;
                #pragma unroll
                for (int a = 0; a < 8; a++)
                    #pragma unroll
                    for (int q = 0; q < 2; q++)
                        O[a][2*i + q] = O[a][2*i + q] * a0
                                      + buf[4 + a * 4 + 2*i + q] * a1;
            }
            // normalize, split hi/lo, scatter into bug-faithful layout
            #pragma unroll
            for (int i = 0; i < 2; i++) {
                float inv = 1.0f / l_run[i];
                int t   = qi * 128 + wq + (lane >> 2) + 8 * i;
                int col = t & (C_DIM - 1);
                int thi = t >> 10;
                #pragma unroll
                for (int a = 0; a < 8; a++)
                    #pragma unroll
                    for (int q = 0; q < 2; q++) {
                        int d = a * 8 + (lane & 3) * 2 + q;
                        float v = O[a][2*i + q] * inv;
                        __nv_bfloat16 hh = __float2bfloat16(v);
                        int row = h * 128 + 2 * d + thi;
                        size_t idx = (size_t)row * C_DIM + col;
                        Zhi[idx] = hh;
                        Zlo[idx] = __float2bfloat16(v - __bfloat162float(hh));
                    }
            }
        }
    }
}

// ---------------------------------------------------------------------------
extern "C" void kernel_launch(void* const* d_in, const int* in_sizes, int n_in,
                              void* d_out, int out_size)
{
    const float* x      = (const float*)d_in[0];
    const float* w_attn = (const float*)d_in[1];
    const float* b_attn = (const float*)d_in[2];
    const float* w_proj = (const float*)d_in[3];
    const float* b_proj = (const float*)d_in[4];
    float* out = (float*)d_out;

    void *p;
    cudaGetSymbolAddress(&p, g_qkvh); __nv_bfloat16* qh = (__nv_bfloat16*)p;
    cudaGetSymbolAddress(&p, g_qkvl); __nv_bfloat16* ql = (__nv_bfloat16*)p;
    cudaGetSymbolAddress(&p, g_xh);   __nv_bfloat16* xh = (__nv_bfloat16*)p;
    cudaGetSymbolAddress(&p, g_xl);   __nv_bfloat16* xl = (__nv_bfloat16*)p;
    cudaGetSymbolAddress(&p, g_wah);  __nv_bfloat16* wah = (__nv_bfloat16*)p;
    cudaGetSymbolAddress(&p, g_wal);  __nv_bfloat16* wal = (__nv_bfloat16*)p;
    cudaGetSymbolAddress(&p, g_wph);  __nv_bfloat16* wph = (__nv_bfloat16*)p;
    cudaGetSymbolAddress(&p, g_wpl);  __nv_bfloat16* wpl = (__nv_bfloat16*)p;
    cudaGetSymbolAddress(&p, g_zh);   __nv_bfloat16* zh = (__nv_bfloat16*)p;
    cudaGetSymbolAddress(&p, g_zl);   __nv_bfloat16* zl = (__nv_bfloat16*)p;

    // 0) fp32 -> bf16 hi/lo splits
    split_f32<<<(T_DIM * C_DIM) / 1024, 256>>>(x, xh, xl, T_DIM * C_DIM);
    split_f32<<<(QKV_N * C_DIM) / 1024, 256>>>(w_attn, wah, wal, QKV_N * C_DIM);
    split_f32<<<(C_DIM * C_DIM) / 1024, 256>>>(w_proj, wph, wpl, C_DIM * C_DIM);

    constexpr int GEMM_SMEM = 2 * (2 * 128 * 144 + 2 * 64 * 144);  // 110592 B
    cudaFuncSetAttribute(gemm_mma_bf16x3<true>,
                         cudaFuncAttributeMaxDynamicSharedMemorySize, GEMM_SMEM);
    cudaFuncSetAttribute(gemm_mma_bf16x3<false>,
                         cudaFuncAttributeMaxDynamicSharedMemorySize, GEMM_SMEM);

    // 1) QKV projection -> bf16 hi/lo qkv
    {
        dim3 grid(QKV_N / 64, T_DIM / 128);
        gemm_mma_bf16x3<true><<<grid, 256, GEMM_SMEM>>>(
            xh, xl, wah, wal, b_attn, nullptr, qh, ql, T_DIM, QKV_N, C_DIM);
    }

    // 2) Tensor-core flash attention, fused permute, emits bf16 hi/lo z
    {
        constexpr int ATTN_SMEM = (2 + 8) * 128 * 144;   // 184320 B
        cudaFuncSetAttribute(attn_mma,
                             cudaFuncAttributeMaxDynamicSharedMemorySize, ATTN_SMEM);
        dim3 grid(T_DIM / 256, NHEAD);   // 8 x 16 = 128 CTAs, uniform work
        attn_mma<<<grid, 512, ATTN_SMEM>>>(qh, ql, zh, zl);
    }

    // 3) Output projection: (2048,1024) = Z @ w_proj^T + b_proj (fp32 out)
    {
        dim3 grid(C_DIM / 64, T_DIM / 128);
        gemm_mma_bf16x3<false><<<grid, 256, GEMM_SMEM>>>(
            zh, zl, wph, wpl, b_proj, out, nullptr, nullptr, T_DIM, C_DIM, C_DIM);
    }
}

// round 11
// speedup vs baseline: 3.0495x; 1.0410x over previous
#include <cuda_runtime.h>
#include <cuda_fp16.h>
#include <cstdint>

#define T_DIM 2048
#define C_DIM 1024
#define NHEAD 16
#define HDIM  64
#define QKV_N (3 * C_DIM)

// ---------------------------------------------------------------------------
// Scratch (__device__ globals; allocation-free rule)
// ---------------------------------------------------------------------------
__device__ __half g_qkvh[T_DIM * QKV_N], g_qkvl[T_DIM * QKV_N];
__device__ __half g_xh[T_DIM * C_DIM],  g_xl[T_DIM * C_DIM];
__device__ __half g_wah[QKV_N * C_DIM], g_wal[QKV_N * C_DIM];
__device__ __half g_wph[C_DIM * C_DIM], g_wpl[C_DIM * C_DIM];
__device__ __half g_zh[T_DIM * C_DIM],  g_zl[T_DIM * C_DIM];
__device__ unsigned int g_ctr[2];

// ---------------------------------------------------------------------------
// PTX helpers — sm_80-era only (harness stages PTX at compute_103)
// ---------------------------------------------------------------------------
__device__ __forceinline__ uint32_t smem_u32(const void* p) {
    uint32_t a;
    asm("{ .reg .u64 t; cvta.to.shared.u64 t, %1; cvt.u32.u64 %0, t; }"
        : "=r"(a) : "l"(p));
    return a;
}
__device__ __forceinline__ void cp_async16(uint32_t s, const void* g) {
    asm volatile("cp.async.cg.shared.global [%0], [%1], 16;" :: "r"(s), "l"(g));
}
#define CP_COMMIT() asm volatile("cp.async.commit_group;" ::: "memory")
#define CP_WAIT1()  asm volatile("cp.async.wait_group 1;" ::: "memory")
#define CP_WAIT0()  asm volatile("cp.async.wait_group 0;" ::: "memory")

#define LDM4(R, addr) \
    asm volatile("ldmatrix.sync.aligned.m8n8.x4.shared.b16 {%0,%1,%2,%3}, [%4];" \
        : "=r"((R)[0]), "=r"((R)[1]), "=r"((R)[2]), "=r"((R)[3]) : "r"(addr))
#define LDMT4(R, addr) \
    asm volatile("ldmatrix.sync.aligned.m8n8.x4.trans.shared.b16 {%0,%1,%2,%3}, [%4];" \
        : "=r"((R)[0]), "=r"((R)[1]), "=r"((R)[2]), "=r"((R)[3]) : "r"(addr))

#define MMA16816(c, a, b0, b1) \
    asm volatile("mma.sync.aligned.m16n8k16.row.col.f32.f16.f16.f32 " \
        "{%0,%1,%2,%3}, {%4,%5,%6,%7}, {%8,%9}, {%0,%1,%2,%3};" \
        : "+f"((c)[0]), "+f"((c)[1]), "+f"((c)[2]), "+f"((c)[3]) \
        : "r"((a)[0]), "r"((a)[1]), "r"((a)[2]), "r"((a)[3]), "r"(b0), "r"(b1))

__device__ __forceinline__ uint32_t pack_h2(float x, float y) {
    __half hx = __float2half_rn(x), hy = __float2half_rn(y);
    uint16_t ux = *(uint16_t*)&hx, uy = *(uint16_t*)&hy;
    return (uint32_t)ux | ((uint32_t)uy << 16);
}
__device__ __forceinline__ void pack_hilo(float x, float y,
                                          uint32_t& hi, uint32_t& lo) {
    __half hx = __float2half_rn(x), hy = __float2half_rn(y);
    __half lx = __float2half_rn(x - __half2float(hx));
    __half ly = __float2half_rn(y - __half2float(hy));
    uint16_t a = *(uint16_t*)&hx, b = *(uint16_t*)&hy;
    uint16_t c = *(uint16_t*)&lx, d = *(uint16_t*)&ly;
    hi = (uint32_t)a | ((uint32_t)b << 16);
    lo = (uint32_t)c | ((uint32_t)d << 16);
}

// ---------------------------------------------------------------------------
__global__ void reset_ctr() { g_ctr[0] = 0; g_ctr[1] = 0; }

// fp32 -> (hi, lo) fp16 split
__global__ __launch_bounds__(256) void split_f32(
    const float* __restrict__ src, __half* __restrict__ hi,
    __half* __restrict__ lo, int n)
{
    int i = (blockIdx.x * 256 + threadIdx.x) * 4;
    if (i >= n) return;
    float4 v = *(const float4*)(src + i);
    float vv[4] = {v.x, v.y, v.z, v.w};
    #pragma unroll
    for (int j = 0; j < 4; j++) {
        __half h = __float2half_rn(vv[j]);
        hi[i + j] = h;
        lo[i + j] = __float2half_rn(vv[j] - __half2float(h));
    }
}

// ---------------------------------------------------------------------------
// Persistent work-stealing mma.sync NT GEMM, fp16 3-pass split + bias.
// 128x64 tiles, 256 threads, 2 CTAs/SM; CTAs grab tiles via global counter.
// ---------------------------------------------------------------------------
template <bool SPLIT_OUT>
__global__ __launch_bounds__(256, 2) void gemm_mma_fp16x3(
    const __half* __restrict__ Ahi, const __half* __restrict__ Alo,
    const __half* __restrict__ Bhi, const __half* __restrict__ Blo,
    const float* __restrict__ bias, float* __restrict__ C,
    __half* __restrict__ Ch, __half* __restrict__ Cl,
    int N, int K, int ntn, int ntiles, int ctr_idx)
{
    constexpr int PITCHB = 144;
    constexpr int A_MAT  = 128 * PITCHB;
    constexpr int B_MAT  = 64 * PITCHB;
    constexpr int OFF_AH = 0, OFF_AL = A_MAT;
    constexpr int OFF_BH = 2 * A_MAT, OFF_BL = 2 * A_MAT + B_MAT;
    constexpr int STAGE  = 2 * A_MAT + 2 * B_MAT;   // 55296
    constexpr int TSLOT  = 2 * STAGE;               // tile-broadcast slot

    extern __shared__ char smem[];
    const uint32_t base = smem_u32(smem);

    const int tid  = threadIdx.x;
    const int warp = tid >> 5, lane = tid & 31;
    const int wm = warp & 3, wn = warp >> 2;

    const uint32_t a_row = (uint32_t)(wm * 32 + ((lane >> 3) & 1) * 8 + (lane & 7));
    const uint32_t a_ko  = (uint32_t)((lane >> 4) * 8);
    const uint32_t b_row = (uint32_t)(wn * 32 + (lane >> 4) * 8 + (lane & 7));
    const uint32_t b_ko  = (uint32_t)(((lane >> 3) & 1) * 8);

    for (;;) {
        if (tid == 0)
            *(volatile unsigned int*)(smem + TSLOT) = atomicAdd(&g_ctr[ctr_idx], 1u);
        __syncthreads();
        const unsigned int t = *(volatile unsigned int*)(smem + TSLOT);
        if (t >= (unsigned)ntiles) break;
        const int bm = (int)(t / ntn) * 128;
        const int bn = (int)(t % ntn) * 64;

        auto load_chunk = [&](int c) {
            const uint32_t st = base + (uint32_t)(c & 1) * STAGE;
            const int k0 = c * 64;
            #pragma unroll
            for (int j = 0; j < 4; j++) {
                int g = tid + 256 * j;
                int r = g >> 3, sg = g & 7;
                uint32_t so = (uint32_t)(r * PITCHB + sg * 16);
                size_t ga = (size_t)(bm + r) * K + k0 + sg * 8;
                cp_async16(st + OFF_AH + so, Ahi + ga);
                cp_async16(st + OFF_AL + so, Alo + ga);
            }
            #pragma unroll
            for (int j = 0; j < 2; j++) {
                int g = tid + 256 * j;
                int r = g >> 3, sg = g & 7;
                uint32_t so = (uint32_t)(r * PITCHB + sg * 16);
                size_t gb = (size_t)(bn + r) * K + k0 + sg * 8;
                cp_async16(st + OFF_BH + so, Bhi + gb);
                cp_async16(st + OFF_BL + so, Blo + gb);
            }
            CP_COMMIT();
        };

        float acc[2][4][4];
        #pragma unroll
        for (int mi = 0; mi < 2; mi++)
            #pragma unroll
            for (int ni = 0; ni < 4; ni++)
                #pragma unroll
                for (int q = 0; q < 4; q++) acc[mi][ni][q] = 0.f;

        const int nch = K / 64;
        load_chunk(0);

        for (int c = 0; c < nch; c++) {
            if (c + 1 < nch) { load_chunk(c + 1); CP_WAIT1(); }
            else             { CP_WAIT0(); }
            __syncthreads();

            const uint32_t st = base + (uint32_t)(c & 1) * STAGE;
            #pragma unroll
            for (int ks = 0; ks < 4; ks++) {
                uint32_t Ah[2][4], Al[2][4], Bh[2][4], Bl[2][4];
                #pragma unroll
                for (int mi = 0; mi < 2; mi++) {
                    uint32_t ao = (a_row + mi * 16) * PITCHB + (ks * 16 + a_ko) * 2;
                    LDM4(Ah[mi], st + OFF_AH + ao);
                    LDM4(Al[mi], st + OFF_AL + ao);
                }
                #pragma unroll
                for (int nt = 0; nt < 2; nt++) {
                    uint32_t bo = (b_row + nt * 16) * PITCHB + (ks * 16 + b_ko) * 2;
                    LDM4(Bh[nt], st + OFF_BH + bo);
                    LDM4(Bl[nt], st + OFF_BL + bo);
                }
                #pragma unroll
                for (int mi = 0; mi < 2; mi++)
                    #pragma unroll
                    for (int ni = 0; ni < 4; ni++) {
                        const uint32_t bh0 = Bh[ni >> 1][(ni & 1) * 2];
                        const uint32_t bh1 = Bh[ni >> 1][(ni & 1) * 2 + 1];
                        const uint32_t bl0 = Bl[ni >> 1][(ni & 1) * 2];
                        const uint32_t bl1 = Bl[ni >> 1][(ni & 1) * 2 + 1];
                        MMA16816(acc[mi][ni], Ah[mi], bh0, bh1);
                        MMA16816(acc[mi][ni], Ah[mi], bl0, bl1);
                        MMA16816(acc[mi][ni], Al[mi], bh0, bh1);
                    }
            }
            __syncthreads();
        }

        const int r0 = bm + wm * 32 + (lane >> 2);
        const int c0 = bn + wn * 32 + (lane & 3) * 2;
        #pragma unroll
        for (int mi = 0; mi < 2; mi++)
            #pragma unroll
            for (int ni = 0; ni < 4; ni++) {
                int row = r0 + mi * 16;
                int col = c0 + ni * 8;
                float2 b2 = *(const float2*)(bias + col);
                float v0 = acc[mi][ni][0] + b2.x, v1 = acc[mi][ni][1] + b2.y;
                float v2 = acc[mi][ni][2] + b2.x, v3 = acc[mi][ni][3] + b2.y;
                if (!SPLIT_OUT) {
                    *(float2*)(C + (size_t)row * N + col)       = make_float2(v0, v1);
                    *(float2*)(C + (size_t)(row + 8) * N + col) = make_float2(v2, v3);
                } else {
                    uint32_t h0, l0, h1, l1;
                    pack_hilo(v0, v1, h0, l0);
                    pack_hilo(v2, v3, h1, l1);
                    *(uint32_t*)(Ch + (size_t)row * N + col)       = h0;
                    *(uint32_t*)(Cl + (size_t)row * N + col)       = l0;
                    *(uint32_t*)(Ch + (size_t)(row + 8) * N + col) = h1;
                    *(uint32_t*)(Cl + (size_t)(row + 8) * N + col) = l1;
                }
            }
        // no sync needed: epilogue touches only registers/gmem; counter slot
        // rewrite is fenced by the next iteration's __syncthreads
    }
}

// ---------------------------------------------------------------------------
// Tensor-core flash attention, fp16: S 3-pass (Q,K hi/lo), O 2-pass
// (P single fp16, V hi/lo). Split-key warp groups + paired q-tiles.
// Emits z hi/lo into the bug-faithful layout:
//   Z[h*128 + 2*d + (t>>10)][t & 1023] = y[h][t][d]
// ---------------------------------------------------------------------------
__global__ __launch_bounds__(512, 1) void attn_mma(
    const __half* __restrict__ qkvh, const __half* __restrict__ qkvl,
    __half* __restrict__ Zhi, __half* __restrict__ Zlo)
{
    constexpr int PITCH = 144;
    constexpr int MAT   = 128 * PITCH;
    constexpr int QH_OFF = 0, QL_OFF = MAT;
    constexpr int ST0 = 2 * MAT;
    constexpr int KH = 0, KL = MAT, VH = 2 * MAT, VL = 3 * MAT;
    constexpr int STAGE = 4 * MAT;

    extern __shared__ char smem[];
    const uint32_t base = smem_u32(smem);
    float* mergebuf = (float*)smem;

    const int tid  = threadIdx.x;
    const int warp = tid >> 5, lane = tid & 31;
    const int grp  = warp >> 3;
    const int wg   = warp & 7;
    const int wq   = wg * 16;
    const int kh   = grp * 64;
    const int h    = blockIdx.y;

    const float NEG_INF = __int_as_float(0xff800000);

    const uint32_t a_rl = (uint32_t)(((lane >> 3) & 1) * 8 + (lane & 7));
    const uint32_t a_ko = (uint32_t)((lane >> 4) * 8);
    const uint32_t b_rl = (uint32_t)((lane >> 4) * 8 + (lane & 7));
    const uint32_t b_ko = (uint32_t)(((lane >> 3) & 1) * 8);

    for (int pass = 0; pass < 2; pass++) {
        const int qi = pass == 0 ? (15 - (int)blockIdx.x) : (int)blockIdx.x;

        __syncthreads();

        #pragma unroll
        for (int j = 0; j < 2; j++) {
            int g = tid + 512 * j;
            int r = g >> 3, sg = g & 7;
            uint32_t so = (uint32_t)(r * PITCH + sg * 16);
            size_t ga = (size_t)(qi * 128 + r) * QKV_N + h * HDIM + sg * 8;
            cp_async16(base + QH_OFF + so, qkvh + ga);
            cp_async16(base + QL_OFF + so, qkvl + ga);
        }
        auto load_kv = [&](int kt) {
            const uint32_t st = base + ST0 + (uint32_t)(kt & 1) * STAGE;
            #pragma unroll
            for (int j = 0; j < 2; j++) {
                int g = tid + 512 * j;
                int r = g >> 3, sg = g & 7;
                uint32_t so = (uint32_t)(r * PITCH + sg * 16);
                size_t gk = (size_t)(kt * 128 + r) * QKV_N + C_DIM     + h * HDIM + sg * 8;
                size_t gv = (size_t)(kt * 128 + r) * QKV_N + 2 * C_DIM + h * HDIM + sg * 8;
                cp_async16(st + KH + so, qkvh + gk);
                cp_async16(st + KL + so, qkvl + gk);
                cp_async16(st + VH + so, qkvh + gv);
                cp_async16(st + VL + so, qkvl + gv);
            }
        };
        load_kv(0);
        CP_COMMIT();

        float m_run[2] = {-1e30f, -1e30f};
        float l_run[2] = {0.f, 0.f};
        float O[8][4];
        #pragma unroll
        for (int a = 0; a < 8; a++)
            #pragma unroll
            for (int q = 0; q < 4; q++) O[a][q] = 0.f;

        for (int kt = 0; kt <= qi; kt++) {
            __syncthreads();
            if (kt + 1 <= qi) { load_kv(kt + 1); CP_COMMIT(); CP_WAIT1(); }
            else              { CP_WAIT0(); }
            __syncthreads();

            const uint32_t sk = base + ST0 + (uint32_t)(kt & 1) * STAGE;

            float S[8][4];
            #pragma unroll
            for (int a = 0; a < 8; a++)
                #pragma unroll
                for (int q = 0; q < 4; q++) S[a][q] = 0.f;

            #pragma unroll
            for (int ks = 0; ks < 4; ks++) {
                uint32_t Ah[4], Al[4];
                uint32_t ao = (wq + a_rl) * PITCH + (ks * 16 + a_ko) * 2;
                LDM4(Ah, base + QH_OFF + ao);
                LDM4(Al, base + QL_OFF + ao);
                #pragma unroll
                for (int ng = 0; ng < 4; ng++) {
                    uint32_t Bh[4], Bl[4];
                    uint32_t bo = (kh + ng * 16 + b_rl) * PITCH + (ks * 16 + b_ko) * 2;
                    LDM4(Bh, sk + KH + bo);
                    LDM4(Bl, sk + KL + bo);
                    MMA16816(S[2*ng],   Ah, Bh[0], Bh[1]);
                    MMA16816(S[2*ng+1], Ah, Bh[2], Bh[3]);
                    MMA16816(S[2*ng],   Ah, Bl[0], Bl[1]);
                    MMA16816(S[2*ng+1], Ah, Bl[2], Bl[3]);
                    MMA16816(S[2*ng],   Al, Bh[0], Bh[1]);
                    MMA16816(S[2*ng+1], Al, Bh[2], Bh[3]);
                }
            }
            #pragma unroll
            for (int a = 0; a < 8; a++)
                #pragma unroll
                for (int q = 0; q < 4; q++) S[a][q] *= 0.125f;

            if (kt == qi) {
                int rbase = qi * 128 + wq + (lane >> 2);
                int cbase = kt * 128 + kh + (lane & 3) * 2;
                #pragma unroll
                for (int a = 0; a < 8; a++)
                    #pragma unroll
                    for (int q = 0; q < 4; q++) {
                        int row = rbase + (q >= 2 ? 8 : 0);
                        int col = cbase + a * 8 + (q & 1);
                        if (col > row) S[a][q] = NEG_INF;
                    }
            }

            #pragma unroll
            for (int i = 0; i < 2; i++) {
                float mx = NEG_INF;
                #pragma unroll
                for (int a = 0; a < 8; a++)
                    mx = fmaxf(mx, fmaxf(S[a][2*i], S[a][2*i+1]));
                mx = fmaxf(mx, __shfl_xor_sync(0xffffffffu, mx, 1));
                mx = fmaxf(mx, __shfl_xor_sync(0xffffffffu, mx, 2));
                float mn = fmaxf(m_run[i], mx);
                float alpha = __expf(m_run[i] - mn);
                float sum = 0.f;
                #pragma unroll
                for (int a = 0; a < 8; a++) {
                    float p0 = __expf(S[a][2*i]   - mn);
                    float p1 = __expf(S[a][2*i+1] - mn);
                    S[a][2*i] = p0; S[a][2*i+1] = p1;
                    sum += p0 + p1;
                }
                sum += __shfl_xor_sync(0xffffffffu, sum, 1);
                sum += __shfl_xor_sync(0xffffffffu, sum, 2);
                l_run[i] = l_run[i] * alpha + sum;
                m_run[i] = mn;
                #pragma unroll
                for (int a = 0; a < 8; a++) {
                    O[a][2*i]   *= alpha;
                    O[a][2*i+1] *= alpha;
                }
            }

            // P -> single-fp16 A-fragments
            uint32_t Ph[4][4];
            #pragma unroll
            for (int kc = 0; kc < 4; kc++) {
                Ph[kc][0] = pack_h2(S[2*kc][0],   S[2*kc][1]);
                Ph[kc][1] = pack_h2(S[2*kc][2],   S[2*kc][3]);
                Ph[kc][2] = pack_h2(S[2*kc+1][0], S[2*kc+1][1]);
                Ph[kc][3] = pack_h2(S[2*kc+1][2], S[2*kc+1][3]);
            }

            // O += P (Vh + Vl): 2-pass
            #pragma unroll
            for (int kc = 0; kc < 4; kc++) {
                uint32_t krow = (uint32_t)(kh + kc * 16) + a_rl;
                #pragma unroll
                for (int dg = 0; dg < 4; dg++) {
                    uint32_t Vh4[4], Vl4[4];
                    uint32_t vo = krow * PITCH + (dg * 16 + a_ko) * 2;
                    LDMT4(Vh4, sk + VH + vo);
                    LDMT4(Vl4, sk + VL + vo);
                    MMA16816(O[2*dg],   Ph[kc], Vh4[0], Vh4[1]);
                    MMA16816(O[2*dg+1], Ph[kc], Vh4[2], Vh4[3]);
                    MMA16816(O[2*dg],   Ph[kc], Vl4[0], Vl4[1]);
                    MMA16816(O[2*dg+1], Ph[kc], Vl4[2], Vl4[3]);
                }
            }
        }

        __syncthreads();
        const int slot = wg * 32 + lane;
        float* buf = mergebuf + slot * 37;
        if (grp == 1) {
            buf[0] = m_run[0]; buf[1] = m_run[1];
            buf[2] = l_run[0]; buf[3] = l_run[1];
            #pragma unroll
            for (int a = 0; a < 8; a++)
                #pragma unroll
                for (int q = 0; q < 4; q++) buf[4 + a * 4 + q] = O[a][q];
        }
        __syncthreads();
        if (grp == 0) {
            #pragma unroll
            for (int i = 0; i < 2; i++) {
                float m1 = buf[i], l1 = buf[2 + i];
                float m = fmaxf(m_run[i], m1);
                float a0 = __expf(m_run[i] - m);
                float a1 = __expf(m1 - m);
                l_run[i] = l_run[i] * a0 + l1 * a1;
                #pragma unroll
                for (int a = 0; a < 8; a++)
                    #pragma unroll
                    for (int q = 0; q < 2; q++)
                        O[a][2*i + q] = O[a][2*i + q] * a0
                                      + buf[4 + a * 4 + 2*i + q] * a1;
            }
            #pragma unroll
            for (int i = 0; i < 2; i++) {
                float inv = 1.0f / l_run[i];
                int t   = qi * 128 + wq + (lane >> 2) + 8 * i;
                int col = t & (C_DIM - 1);
                int thi = t >> 10;
                #pragma unroll
                for (int a = 0; a < 8; a++)
                    #pragma unroll
                    for (int q = 0; q < 2; q++) {
                        int d = a * 8 + (lane & 3) * 2 + q;
                        float v = O[a][2*i + q] * inv;
                        __half hh = __float2half_rn(v);
                        int row = h * 128 + 2 * d + thi;
                        size_t idx = (size_t)row * C_DIM + col;
                        Zhi[idx] = hh;
                        Zlo[idx] = __float2half_rn(v - __half2float(hh));
                    }
            }
        }
    }
}

// ---------------------------------------------------------------------------
extern "C" void kernel_launch(void* const* d_in, const int* in_sizes, int n_in,
                              void* d_out, int out_size)
{
    const float* x      = (const float*)d_in[0];
    const float* w_attn = (const float*)d_in[1];
    const float* b_attn = (const float*)d_in[2];
    const float* w_proj = (const float*)d_in[3];
    const float* b_proj = (const float*)d_in[4];
    float* out = (float*)d_out;

    void *p;
    cudaGetSymbolAddress(&p, g_qkvh); __half* qh = (__half*)p;
    cudaGetSymbolAddress(&p, g_qkvl); __half* ql = (__half*)p;
    cudaGetSymbolAddress(&p, g_xh);   __half* xh = (__half*)p;
    cudaGetSymbolAddress(&p, g_xl);   __half* xl = (__half*)p;
    cudaGetSymbolAddress(&p, g_wah);  __half* wah = (__half*)p;
    cudaGetSymbolAddress(&p, g_wal);  __half* wal = (__half*)p;
    cudaGetSymbolAddress(&p, g_wph);  __half* wph = (__half*)p;
    cudaGetSymbolAddress(&p, g_wpl);  __half* wpl = (__half*)p;
    cudaGetSymbolAddress(&p, g_zh);   __half* zh = (__half*)p;
    cudaGetSymbolAddress(&p, g_zl);   __half* zl = (__half*)p;

    reset_ctr<<<1, 1>>>();

    split_f32<<<(T_DIM * C_DIM) / 1024, 256>>>(x, xh, xl, T_DIM * C_DIM);
    split_f32<<<(QKV_N * C_DIM) / 1024, 256>>>(w_attn, wah, wal, QKV_N * C_DIM);
    split_f32<<<(C_DIM * C_DIM) / 1024, 256>>>(w_proj, wph, wpl, C_DIM * C_DIM);

    constexpr int GEMM_SMEM = 2 * (2 * 128 * 144 + 2 * 64 * 144) + 16;  // 110608
    cudaFuncSetAttribute(gemm_mma_fp16x3<true>,
                         cudaFuncAttributeMaxDynamicSharedMemorySize, GEMM_SMEM);
    cudaFuncSetAttribute(gemm_mma_fp16x3<false>,
                         cudaFuncAttributeMaxDynamicSharedMemorySize, GEMM_SMEM);

    // 1) QKV projection -> fp16 hi/lo qkv (persistent, counter 0)
    gemm_mma_fp16x3<true><<<296, 256, GEMM_SMEM>>>(
        xh, xl, wah, wal, b_attn, nullptr, qh, ql,
        QKV_N, C_DIM, QKV_N / 64, (T_DIM / 128) * (QKV_N / 64), 0);

    // 2) Tensor-core flash attention, fused permute, emits fp16 hi/lo z
    {
        constexpr int ATTN_SMEM = (2 + 8) * 128 * 144;   // 184320 B
        cudaFuncSetAttribute(attn_mma,
                             cudaFuncAttributeMaxDynamicSharedMemorySize, ATTN_SMEM);
        dim3 grid(T_DIM / 256, NHEAD);
        attn_mma<<<grid, 512, ATTN_SMEM>>>(qh, ql, zh, zl);
    }

    // 3) Output projection (persistent, counter 1, fp32 out)
    gemm_mma_fp16x3<false><<<296, 256, GEMM_SMEM>>>(
        zh, zl, wph, wpl, b_proj, out, nullptr, nullptr,
        C_DIM, C_DIM, C_DIM / 64, (T_DIM / 128) * (C_DIM / 64), 1);
}

// round 14
// speedup vs baseline: 4.1104x; 1.3479x over previous
#include <cuda_runtime.h>
#include <cuda_fp16.h>
#include <cstdint>

#define T_DIM 2048
#define C_DIM 1024
#define NHEAD 16
#define HDIM  64
#define QKV_N (3 * C_DIM)

// ---------------------------------------------------------------------------
// Scratch (__device__ globals; allocation-free rule)
// ---------------------------------------------------------------------------
__device__ __half g_qkvh[T_DIM * QKV_N], g_qkvl[T_DIM * QKV_N];
__device__ __half g_xh[T_DIM * C_DIM];
__device__ __half g_wah[QKV_N * C_DIM], g_wal[QKV_N * C_DIM];
__device__ __half g_wph[C_DIM * C_DIM], g_wpl[C_DIM * C_DIM];
__device__ __half g_zh[T_DIM * C_DIM];
__device__ unsigned int g_ctr[2];

// ---------------------------------------------------------------------------
// PTX helpers — sm_80-era only (harness stages PTX at compute_103)
// ---------------------------------------------------------------------------
__device__ __forceinline__ uint32_t smem_u32(const void* p) {
    uint32_t a;
    asm("{ .reg .u64 t; cvta.to.shared.u64 t, %1; cvt.u32.u64 %0, t; }"
        : "=r"(a) : "l"(p));
    return a;
}
__device__ __forceinline__ void cp_async16(uint32_t s, const void* g) {
    asm volatile("cp.async.cg.shared.global [%0], [%1], 16;" :: "r"(s), "l"(g));
}
#define CP_COMMIT() asm volatile("cp.async.commit_group;" ::: "memory")
#define CP_WAIT1()  asm volatile("cp.async.wait_group 1;" ::: "memory")
#define CP_WAIT0()  asm volatile("cp.async.wait_group 0;" ::: "memory")

#define LDM4(R, addr) \
    asm volatile("ldmatrix.sync.aligned.m8n8.x4.shared.b16 {%0,%1,%2,%3}, [%4];" \
        : "=r"((R)[0]), "=r"((R)[1]), "=r"((R)[2]), "=r"((R)[3]) : "r"(addr))
#define LDMT4(R, addr) \
    asm volatile("ldmatrix.sync.aligned.m8n8.x4.trans.shared.b16 {%0,%1,%2,%3}, [%4];" \
        : "=r"((R)[0]), "=r"((R)[1]), "=r"((R)[2]), "=r"((R)[3]) : "r"(addr))

#define MMA16816(c, a, b0, b1) \
    asm volatile("mma.sync.aligned.m16n8k16.row.col.f32.f16.f16.f32 " \
        "{%0,%1,%2,%3}, {%4,%5,%6,%7}, {%8,%9}, {%0,%1,%2,%3};" \
        : "+f"((c)[0]), "+f"((c)[1]), "+f"((c)[2]), "+f"((c)[3]) \
        : "r"((a)[0]), "r"((a)[1]), "r"((a)[2]), "r"((a)[3]), "r"(b0), "r"(b1))

__device__ __forceinline__ uint32_t pack_h2(float x, float y) {
    __half hx = __float2half_rn(x), hy = __float2half_rn(y);
    uint16_t ux = *(uint16_t*)&hx, uy = *(uint16_t*)&hy;
    return (uint32_t)ux | ((uint32_t)uy << 16);
}
__device__ __forceinline__ void pack_hilo(float x, float y,
                                          uint32_t& hi, uint32_t& lo) {
    __half hx = __float2half_rn(x), hy = __float2half_rn(y);
    __half lx = __float2half_rn(x - __half2float(hx));
    __half ly = __float2half_rn(y - __half2float(hy));
    uint16_t a = *(uint16_t*)&hx, b = *(uint16_t*)&hy;
    uint16_t c = *(uint16_t*)&lx, d = *(uint16_t*)&ly;
    hi = (uint32_t)a | ((uint32_t)b << 16);
    lo = (uint32_t)c | ((uint32_t)d << 16);
}

// ---------------------------------------------------------------------------
// fp32 -> fp16 hi-only split (for A-side operands); also resets tile counters
__global__ __launch_bounds__(256) void split_hi(
    const float* __restrict__ src, __half* __restrict__ hi, int n)
{
    if (blockIdx.x == 0 && threadIdx.x == 0) { g_ctr[0] = 0; g_ctr[1] = 0; }
    int i = (blockIdx.x * 256 + threadIdx.x) * 4;
    if (i >= n) return;
    float4 v = *(const float4*)(src + i);
    __half2* h2 = (__half2*)(hi + i);
    h2[0] = __floats2half2_rn(v.x, v.y);
    h2[1] = __floats2half2_rn(v.z, v.w);
}

// fp32 -> (hi, lo) fp16 split (for weights / B-side)
__global__ __launch_bounds__(256) void split_f32(
    const float* __restrict__ src, __half* __restrict__ hi,
    __half* __restrict__ lo, int n)
{
    int i = (blockIdx.x * 256 + threadIdx.x) * 4;
    if (i >= n) return;
    float4 v = *(const float4*)(src + i);
    float vv[4] = {v.x, v.y, v.z, v.w};
    #pragma unroll
    for (int j = 0; j < 4; j++) {
        __half h = __float2half_rn(vv[j]);
        hi[i + j] = h;
        lo[i + j] = __float2half_rn(vv[j] - __half2float(h));
    }
}

// ---------------------------------------------------------------------------
// Persistent work-stealing mma.sync NT GEMM, 2-pass: D = Ah*(Bh + Bl) + bias.
// 128x64 tiles, 256 threads, 2 CTAs/SM.
// ---------------------------------------------------------------------------
template <bool SPLIT_OUT>
__global__ __launch_bounds__(256, 2) void gemm_mma_fp16x2(
    const __half* __restrict__ Ahi,
    const __half* __restrict__ Bhi, const __half* __restrict__ Blo,
    const float* __restrict__ bias, float* __restrict__ C,
    __half* __restrict__ Ch, __half* __restrict__ Cl,
    int N, int K, int ntn, int ntiles, int ctr_idx)
{
    constexpr int PITCHB = 144;
    constexpr int A_MAT  = 128 * PITCHB;            // 18432
    constexpr int B_MAT  = 64 * PITCHB;             // 9216
    constexpr int OFF_A  = 0;
    constexpr int OFF_BH = A_MAT, OFF_BL = A_MAT + B_MAT;
    constexpr int STAGE  = A_MAT + 2 * B_MAT;       // 36864
    constexpr int TSLOT  = 2 * STAGE;

    extern __shared__ char smem[];
    const uint32_t base = smem_u32(smem);

    const int tid  = threadIdx.x;
    const int warp = tid >> 5, lane = tid & 31;
    const int wm = warp & 3, wn = warp >> 2;

    const uint32_t a_row = (uint32_t)(wm * 32 + ((lane >> 3) & 1) * 8 + (lane & 7));
    const uint32_t a_ko  = (uint32_t)((lane >> 4) * 8);
    const uint32_t b_row = (uint32_t)(wn * 32 + (lane >> 4) * 8 + (lane & 7));
    const uint32_t b_ko  = (uint32_t)(((lane >> 3) & 1) * 8);

    for (;;) {
        if (tid == 0)
            *(volatile unsigned int*)(smem + TSLOT) = atomicAdd(&g_ctr[ctr_idx], 1u);
        __syncthreads();
        const unsigned int t = *(volatile unsigned int*)(smem + TSLOT);
        if (t >= (unsigned)ntiles) break;
        const int bm = (int)(t / ntn) * 128;
        const int bn = (int)(t % ntn) * 64;

        auto load_chunk = [&](int c) {
            const uint32_t st = base + (uint32_t)(c & 1) * STAGE;
            const int k0 = c * 64;
            #pragma unroll
            for (int j = 0; j < 4; j++) {               // A hi: 1024 segs
                int g = tid + 256 * j;
                int r = g >> 3, sg = g & 7;
                uint32_t so = (uint32_t)(r * PITCHB + sg * 16);
                cp_async16(st + OFF_A + so,
                           Ahi + (size_t)(bm + r) * K + k0 + sg * 8);
            }
            #pragma unroll
            for (int j = 0; j < 2; j++) {               // B hi+lo: 512 segs ea
                int g = tid + 256 * j;
                int r = g >> 3, sg = g & 7;
                uint32_t so = (uint32_t)(r * PITCHB + sg * 16);
                size_t gb = (size_t)(bn + r) * K + k0 + sg * 8;
                cp_async16(st + OFF_BH + so, Bhi + gb);
                cp_async16(st + OFF_BL + so, Blo + gb);
            }
            CP_COMMIT();
        };

        float acc[2][4][4];
        #pragma unroll
        for (int mi = 0; mi < 2; mi++)
            #pragma unroll
            for (int ni = 0; ni < 4; ni++)
                #pragma unroll
                for (int q = 0; q < 4; q++) acc[mi][ni][q] = 0.f;

        const int nch = K / 64;
        load_chunk(0);

        for (int c = 0; c < nch; c++) {
            if (c + 1 < nch) { load_chunk(c + 1); CP_WAIT1(); }
            else             { CP_WAIT0(); }
            __syncthreads();

            const uint32_t st = base + (uint32_t)(c & 1) * STAGE;
            #pragma unroll
            for (int ks = 0; ks < 4; ks++) {
                uint32_t Ah[2][4], Bh[2][4], Bl[2][4];
                #pragma unroll
                for (int mi = 0; mi < 2; mi++) {
                    uint32_t ao = (a_row + mi * 16) * PITCHB + (ks * 16 + a_ko) * 2;
                    LDM4(Ah[mi], st + OFF_A + ao);
                }
                #pragma unroll
                for (int nt = 0; nt < 2; nt++) {
                    uint32_t bo = (b_row + nt * 16) * PITCHB + (ks * 16 + b_ko) * 2;
                    LDM4(Bh[nt], st + OFF_BH + bo);
                    LDM4(Bl[nt], st + OFF_BL + bo);
                }
                #pragma unroll
                for (int mi = 0; mi < 2; mi++)
                    #pragma unroll
                    for (int ni = 0; ni < 4; ni++) {
                        const uint32_t bh0 = Bh[ni >> 1][(ni & 1) * 2];
                        const uint32_t bh1 = Bh[ni >> 1][(ni & 1) * 2 + 1];
                        const uint32_t bl0 = Bl[ni >> 1][(ni & 1) * 2];
                        const uint32_t bl1 = Bl[ni >> 1][(ni & 1) * 2 + 1];
                        MMA16816(acc[mi][ni], Ah[mi], bh0, bh1);
                        MMA16816(acc[mi][ni], Ah[mi], bl0, bl1);
                    }
            }
            __syncthreads();
        }

        const int r0 = bm + wm * 32 + (lane >> 2);
        const int c0 = bn + wn * 32 + (lane & 3) * 2;
        #pragma unroll
        for (int mi = 0; mi < 2; mi++)
            #pragma unroll
            for (int ni = 0; ni < 4; ni++) {
                int row = r0 + mi * 16;
                int col = c0 + ni * 8;
                float2 b2 = *(const float2*)(bias + col);
                float v0 = acc[mi][ni][0] + b2.x, v1 = acc[mi][ni][1] + b2.y;
                float v2 = acc[mi][ni][2] + b2.x, v3 = acc[mi][ni][3] + b2.y;
                if (!SPLIT_OUT) {
                    *(float2*)(C + (size_t)row * N + col)       = make_float2(v0, v1);
                    *(float2*)(C + (size_t)(row + 8) * N + col) = make_float2(v2, v3);
                } else {
                    uint32_t h0, l0, h1, l1;
                    pack_hilo(v0, v1, h0, l0);
                    pack_hilo(v2, v3, h1, l1);
                    *(uint32_t*)(Ch + (size_t)row * N + col)       = h0;
                    *(uint32_t*)(Cl + (size_t)row * N + col)       = l0;
                    *(uint32_t*)(Ch + (size_t)(row + 8) * N + col) = h1;
                    *(uint32_t*)(Cl + (size_t)(row + 8) * N + col) = l1;
                }
            }
    }
}

// ---------------------------------------------------------------------------
// Tensor-core flash attention, fp16:
//   S = Qh*(Kh + Kl)  (2-pass, Q hi-only)
//   O = P*(Vh + Vl)   (2-pass, P single fp16)
// Split-key warp groups + paired q-tiles; emits z hi-only into the
// bug-faithful layout: Z[h*128 + 2*d + (t>>10)][t & 1023] = y[h][t][d]
// ---------------------------------------------------------------------------
__global__ __launch_bounds__(512, 1) void attn_mma(
    const __half* __restrict__ qkvh, const __half* __restrict__ qkvl,
    __half* __restrict__ Zhi)
{
    constexpr int PITCH = 144;
    constexpr int MAT   = 128 * PITCH;
    constexpr int QH_OFF = 0;
    constexpr int ST0 = MAT;
    constexpr int KH = 0, KL = MAT, VH = 2 * MAT, VL = 3 * MAT;
    constexpr int STAGE = 4 * MAT;

    extern __shared__ char smem[];
    const uint32_t base = smem_u32(smem);
    float* mergebuf = (float*)smem;

    const int tid  = threadIdx.x;
    const int warp = tid >> 5, lane = tid & 31;
    const int grp  = warp >> 3;
    const int wg   = warp & 7;
    const int wq   = wg * 16;
    const int kh   = grp * 64;
    const int h    = blockIdx.y;

    const float NEG_INF = __int_as_float(0xff800000);

    const uint32_t a_rl = (uint32_t)(((lane >> 3) & 1) * 8 + (lane & 7));
    const uint32_t a_ko = (uint32_t)((lane >> 4) * 8);
    const uint32_t b_rl = (uint32_t)((lane >> 4) * 8 + (lane & 7));
    const uint32_t b_ko = (uint32_t)(((lane >> 3) & 1) * 8);

    for (int pass = 0; pass < 2; pass++) {
        const int qi = pass == 0 ? (15 - (int)blockIdx.x) : (int)blockIdx.x;

        __syncthreads();

        #pragma unroll
        for (int j = 0; j < 2; j++) {       // Q hi: 1024 segs
            int g = tid + 512 * j;
            int r = g >> 3, sg = g & 7;
            uint32_t so = (uint32_t)(r * PITCH + sg * 16);
            cp_async16(base + QH_OFF + so,
                       qkvh + (size_t)(qi * 128 + r) * QKV_N + h * HDIM + sg * 8);
        }
        auto load_kv = [&](int kt) {
            const uint32_t st = base + ST0 + (uint32_t)(kt & 1) * STAGE;
            #pragma unroll
            for (int j = 0; j < 2; j++) {
                int g = tid + 512 * j;
                int r = g >> 3, sg = g & 7;
                uint32_t so = (uint32_t)(r * PITCH + sg * 16);
                size_t gk = (size_t)(kt * 128 + r) * QKV_N + C_DIM     + h * HDIM + sg * 8;
                size_t gv = (size_t)(kt * 128 + r) * QKV_N + 2 * C_DIM + h * HDIM + sg * 8;
                cp_async16(st + KH + so, qkvh + gk);
                cp_async16(st + KL + so, qkvl + gk);
                cp_async16(st + VH + so, qkvh + gv);
                cp_async16(st + VL + so, qkvl + gv);
            }
        };
        load_kv(0);
        CP_COMMIT();

        float m_run[2] = {-1e30f, -1e30f};
        float l_run[2] = {0.f, 0.f};
        float O[8][4];
        #pragma unroll
        for (int a = 0; a < 8; a++)
            #pragma unroll
            for (int q = 0; q < 4; q++) O[a][q] = 0.f;

        for (int kt = 0; kt <= qi; kt++) {
            __syncthreads();
            if (kt + 1 <= qi) { load_kv(kt + 1); CP_COMMIT(); CP_WAIT1(); }
            else              { CP_WAIT0(); }
            __syncthreads();

            const uint32_t sk = base + ST0 + (uint32_t)(kt & 1) * STAGE;

            float S[8][4];
            #pragma unroll
            for (int a = 0; a < 8; a++)
                #pragma unroll
                for (int q = 0; q < 4; q++) S[a][q] = 0.f;

            #pragma unroll
            for (int ks = 0; ks < 4; ks++) {
                uint32_t Ah[4];
                uint32_t ao = (wq + a_rl) * PITCH + (ks * 16 + a_ko) * 2;
                LDM4(Ah, base + QH_OFF + ao);
                #pragma unroll
                for (int ng = 0; ng < 4; ng++) {
                    uint32_t Bh[4], Bl[4];
                    uint32_t bo = (kh + ng * 16 + b_rl) * PITCH + (ks * 16 + b_ko) * 2;
                    LDM4(Bh, sk + KH + bo);
                    LDM4(Bl, sk + KL + bo);
                    MMA16816(S[2*ng],   Ah, Bh[0], Bh[1]);
                    MMA16816(S[2*ng+1], Ah, Bh[2], Bh[3]);
                    MMA16816(S[2*ng],   Ah, Bl[0], Bl[1]);
                    MMA16816(S[2*ng+1], Ah, Bl[2], Bl[3]);
                }
            }
            #pragma unroll
            for (int a = 0; a < 8; a++)
                #pragma unroll
                for (int q = 0; q < 4; q++) S[a][q] *= 0.125f;

            if (kt == qi) {
                int rbase = qi * 128 + wq + (lane >> 2);
                int cbase = kt * 128 + kh + (lane & 3) * 2;
                #pragma unroll
                for (int a = 0; a < 8; a++)
                    #pragma unroll
                    for (int q = 0; q < 4; q++) {
                        int row = rbase + (q >= 2 ? 8 : 0);
                        int col = cbase + a * 8 + (q & 1);
                        if (col > row) S[a][q] = NEG_INF;
                    }
            }

            #pragma unroll
            for (int i = 0; i < 2; i++) {
                float mx = NEG_INF;
                #pragma unroll
                for (int a = 0; a < 8; a++)
                    mx = fmaxf(mx, fmaxf(S[a][2*i], S[a][2*i+1]));
                mx = fmaxf(mx, __shfl_xor_sync(0xffffffffu, mx, 1));
                mx = fmaxf(mx, __shfl_xor_sync(0xffffffffu, mx, 2));
                float mn = fmaxf(m_run[i], mx);
                float alpha = __expf(m_run[i] - mn);
                float sum = 0.f;
                #pragma unroll
                for (int a = 0; a < 8; a++) {
                    float p0 = __expf(S[a][2*i]   - mn);
                    float p1 = __expf(S[a][2*i+1] - mn);
                    S[a][2*i] = p0; S[a][2*i+1] = p1;
                    sum += p0 + p1;
                }
                sum += __shfl_xor_sync(0xffffffffu, sum, 1);
                sum += __shfl_xor_sync(0xffffffffu, sum, 2);
                l_run[i] = l_run[i] * alpha + sum;
                m_run[i] = mn;
                #pragma unroll
                for (int a = 0; a < 8; a++) {
                    O[a][2*i]   *= alpha;
                    O[a][2*i+1] *= alpha;
                }
            }

            uint32_t Ph[4][4];
            #pragma unroll
            for (int kc = 0; kc < 4; kc++) {
                Ph[kc][0] = pack_h2(S[2*kc][0],   S[2*kc][1]);
                Ph[kc][1] = pack_h2(S[2*kc][2],   S[2*kc][3]);
                Ph[kc][2] = pack_h2(S[2*kc+1][0], S[2*kc+1][1]);
                Ph[kc][3] = pack_h2(S[2*kc+1][2], S[2*kc+1][3]);
            }

            #pragma unroll
            for (int kc = 0; kc < 4; kc++) {
                uint32_t krow = (uint32_t)(kh + kc * 16) + a_rl;
                #pragma unroll
                for (int dg = 0; dg < 4; dg++) {
                    uint32_t Vh4[4], Vl4[4];
                    uint32_t vo = krow * PITCH + (dg * 16 + a_ko) * 2;
                    LDMT4(Vh4, sk + VH + vo);
                    LDMT4(Vl4, sk + VL + vo);
                    MMA16816(O[2*dg],   Ph[kc], Vh4[0], Vh4[1]);
                    MMA16816(O[2*dg+1], Ph[kc], Vh4[2], Vh4[3]);
                    MMA16816(O[2*dg],   Ph[kc], Vl4[0], Vl4[1]);
                    MMA16816(O[2*dg+1], Ph[kc], Vl4[2], Vl4[3]);
                }
            }
        }

        __syncthreads();
        const int slot = wg * 32 + lane;
        float* buf = mergebuf + slot * 37;
        if (grp == 1) {
            buf[0] = m_run[0]; buf[1] = m_run[1];
            buf[2] = l_run[0]; buf[3] = l_run[1];
            #pragma unroll
            for (int a = 0; a < 8; a++)
                #pragma unroll
                for (int q = 0; q < 4; q++) buf[4 + a * 4 + q] = O[a][q];
        }
        __syncthreads();
        if (grp == 0) {
            #pragma unroll
            for (int i = 0; i < 2; i++) {
                float m1 = buf[i], l1 = buf[2 + i];
                float m = fmaxf(m_run[i], m1);
                float a0 = __expf(m_run[i] - m);
                float a1 = __expf(m1 - m);
                l_run[i] = l_run[i] * a0 + l1 * a1;
                #pragma unroll
                for (int a = 0; a < 8; a++)
                    #pragma unroll
                    for (int q = 0; q < 2; q++)
                        O[a][2*i + q] = O[a][2*i + q] * a0
                                      + buf[4 + a * 4 + 2*i + q] * a1;
            }
            #pragma unroll
            for (int i = 0; i < 2; i++) {
                float inv = 1.0f / l_run[i];
                int t   = qi * 128 + wq + (lane >> 2) + 8 * i;
                int col = t & (C_DIM - 1);
                int thi = t >> 10;
                #pragma unroll
                for (int a = 0; a < 8; a++)
                    #pragma unroll
                    for (int q = 0; q < 2; q++) {
                        int d = a * 8 + (lane & 3) * 2 + q;
                        float v = O[a][2*i + q] * inv;
                        int row = h * 128 + 2 * d + thi;
                        Zhi[(size_t)row * C_DIM + col] = __float2half_rn(v);
                    }
            }
        }
    }
}

// ---------------------------------------------------------------------------
extern "C" void kernel_launch(void* const* d_in, const int* in_sizes, int n_in,
                              void* d_out, int out_size)
{
    const float* x      = (const float*)d_in[0];
    const float* w_attn = (const float*)d_in[1];
    const float* b_attn = (const float*)d_in[2];
    const float* w_proj = (const float*)d_in[3];
    const float* b_proj = (const float*)d_in[4];
    float* out = (float*)d_out;

    void *p;
    cudaGetSymbolAddress(&p, g_qkvh); __half* qh = (__half*)p;
    cudaGetSymbolAddress(&p, g_qkvl); __half* ql = (__half*)p;
    cudaGetSymbolAddress(&p, g_xh);   __half* xh = (__half*)p;
    cudaGetSymbolAddress(&p, g_wah);  __half* wah = (__half*)p;
    cudaGetSymbolAddress(&p, g_wal);  __half* wal = (__half*)p;
    cudaGetSymbolAddress(&p, g_wph);  __half* wph = (__half*)p;
    cudaGetSymbolAddress(&p, g_wpl);  __half* wpl = (__half*)p;
    cudaGetSymbolAddress(&p, g_zh);   __half* zh = (__half*)p;

    // 0) splits (x hi-only also resets tile counters)
    split_hi<<<(T_DIM * C_DIM) / 1024, 256>>>(x, xh, T_DIM * C_DIM);
    split_f32<<<(QKV_N * C_DIM) / 1024, 256>>>(w_attn, wah, wal, QKV_N * C_DIM);
    split_f32<<<(C_DIM * C_DIM) / 1024, 256>>>(w_proj, wph, wpl, C_DIM * C_DIM);

    constexpr int GEMM_SMEM = 2 * (128 * 144 + 2 * 64 * 144) + 16;  // 73744
    cudaFuncSetAttribute(gemm_mma_fp16x2<true>,
                         cudaFuncAttributeMaxDynamicSharedMemorySize, GEMM_SMEM);
    cudaFuncSetAttribute(gemm_mma_fp16x2<false>,
                         cudaFuncAttributeMaxDynamicSharedMemorySize, GEMM_SMEM);

    // 1) QKV projection -> fp16 hi/lo qkv (persistent, counter 0)
    gemm_mma_fp16x2<true><<<296, 256, GEMM_SMEM>>>(
        xh, wah, wal, b_attn, nullptr, qh, ql,
        QKV_N, C_DIM, QKV_N / 64, (T_DIM / 128) * (QKV_N / 64), 0);

    // 2) Tensor-core flash attention -> z hi-only (fused permute)
    {
        constexpr int ATTN_SMEM = 9 * 128 * 144;   // 165888 B
        cudaFuncSetAttribute(attn_mma,
                             cudaFuncAttributeMaxDynamicSharedMemorySize, ATTN_SMEM);
        dim3 grid(T_DIM / 256, NHEAD);
        attn_mma<<<grid, 512, ATTN_SMEM>>>(qh, ql, zh);
    }

    // 3) Output projection (persistent, counter 1, fp32 out)
    gemm_mma_fp16x2<false><<<296, 256, GEMM_SMEM>>>(
        zh, wph, wpl, b_proj, out, nullptr, nullptr,
        C_DIM, C_DIM, C_DIM / 64, (T_DIM / 128) * (C_DIM / 64), 1);
}

// round 16
// speedup vs baseline: 4.5995x; 1.1190x over previous
#include <cuda_runtime.h>
#include <cuda_fp16.h>
#include <cstdint>

#define T_DIM 2048
#define C_DIM 1024
#define NHEAD 16
#define HDIM  64
#define QKV_N (3 * C_DIM)

// ---------------------------------------------------------------------------
// Scratch (__device__ globals; allocation-free rule)
// ---------------------------------------------------------------------------
__device__ __half g_qkvh[T_DIM * QKV_N];
__device__ __half g_xh[T_DIM * C_DIM];
__device__ __half g_wah[QKV_N * C_DIM], g_wal[QKV_N * C_DIM];
__device__ __half g_wph[C_DIM * C_DIM], g_wpl[C_DIM * C_DIM];
__device__ __half g_zh[T_DIM * C_DIM];
__device__ unsigned int g_ctr[2];

// ---------------------------------------------------------------------------
// PTX helpers — sm_80-era only (harness stages PTX at compute_103)
// ---------------------------------------------------------------------------
__device__ __forceinline__ uint32_t smem_u32(const void* p) {
    uint32_t a;
    asm("{ .reg .u64 t; cvta.to.shared.u64 t, %1; cvt.u32.u64 %0, t; }"
        : "=r"(a) : "l"(p));
    return a;
}
__device__ __forceinline__ void cp_async16(uint32_t s, const void* g) {
    asm volatile("cp.async.cg.shared.global [%0], [%1], 16;" :: "r"(s), "l"(g));
}
#define CP_COMMIT() asm volatile("cp.async.commit_group;" ::: "memory")
#define CP_WAIT1()  asm volatile("cp.async.wait_group 1;" ::: "memory")
#define CP_WAIT0()  asm volatile("cp.async.wait_group 0;" ::: "memory")

#define LDM4(R, addr) \
    asm volatile("ldmatrix.sync.aligned.m8n8.x4.shared.b16 {%0,%1,%2,%3}, [%4];" \
        : "=r"((R)[0]), "=r"((R)[1]), "=r"((R)[2]), "=r"((R)[3]) : "r"(addr))
#define LDMT4(R, addr) \
    asm volatile("ldmatrix.sync.aligned.m8n8.x4.trans.shared.b16 {%0,%1,%2,%3}, [%4];" \
        : "=r"((R)[0]), "=r"((R)[1]), "=r"((R)[2]), "=r"((R)[3]) : "r"(addr))

#define MMA16816(c, a, b0, b1) \
    asm volatile("mma.sync.aligned.m16n8k16.row.col.f32.f16.f16.f32 " \
        "{%0,%1,%2,%3}, {%4,%5,%6,%7}, {%8,%9}, {%0,%1,%2,%3};" \
        : "+f"((c)[0]), "+f"((c)[1]), "+f"((c)[2]), "+f"((c)[3]) \
        : "r"((a)[0]), "r"((a)[1]), "r"((a)[2]), "r"((a)[3]), "r"(b0), "r"(b1))

__device__ __forceinline__ uint32_t pack_h2(float x, float y) {
    __half hx = __float2half_rn(x), hy = __float2half_rn(y);
    uint16_t ux = *(uint16_t*)&hx, uy = *(uint16_t*)&hy;
    return (uint32_t)ux | ((uint32_t)uy << 16);
}

// ---------------------------------------------------------------------------
// fp32 -> fp16 hi-only split (A-side operands); also resets tile counters
__global__ __launch_bounds__(256) void split_hi(
    const float* __restrict__ src, __half* __restrict__ hi, int n)
{
    if (blockIdx.x == 0 && threadIdx.x == 0) { g_ctr[0] = 0; g_ctr[1] = 0; }
    int i = (blockIdx.x * 256 + threadIdx.x) * 4;
    if (i >= n) return;
    float4 v = *(const float4*)(src + i);
    __half2* h2 = (__half2*)(hi + i);
    h2[0] = __floats2half2_rn(v.x, v.y);
    h2[1] = __floats2half2_rn(v.z, v.w);
}

// fp32 -> (hi, lo) fp16 split (weights / B-side)
__global__ __launch_bounds__(256) void split_f32(
    const float* __restrict__ src, __half* __restrict__ hi,
    __half* __restrict__ lo, int n)
{
    int i = (blockIdx.x * 256 + threadIdx.x) * 4;
    if (i >= n) return;
    float4 v = *(const float4*)(src + i);
    float vv[4] = {v.x, v.y, v.z, v.w};
    #pragma unroll
    for (int j = 0; j < 4; j++) {
        __half h = __float2half_rn(vv[j]);
        hi[i + j] = h;
        lo[i + j] = __float2half_rn(vv[j] - __half2float(h));
    }
}

// ---------------------------------------------------------------------------
// Persistent work-stealing mma.sync NT GEMM, 2-pass: D = Ah*(Bh + Bl) + bias.
// 128x64 tiles, 256 threads, 2 CTAs/SM. Inner loop split into bh-sweep then
// bl-sweep so accumulator reuse distance is 8 MMAs (no RAW stalls).
// SPLIT_OUT=true: single-fp16 output Ch. SPLIT_OUT=false: fp32 C.
// ---------------------------------------------------------------------------
template <bool SPLIT_OUT>
__global__ __launch_bounds__(256, 2) void gemm_mma_fp16x2(
    const __half* __restrict__ Ahi,
    const __half* __restrict__ Bhi, const __half* __restrict__ Blo,
    const float* __restrict__ bias, float* __restrict__ C,
    __half* __restrict__ Ch,
    int N, int K, int ntn, int ntiles, int ctr_idx)
{
    constexpr int PITCHB = 144;
    constexpr int A_MAT  = 128 * PITCHB;
    constexpr int B_MAT  = 64 * PITCHB;
    constexpr int OFF_A  = 0;
    constexpr int OFF_BH = A_MAT, OFF_BL = A_MAT + B_MAT;
    constexpr int STAGE  = A_MAT + 2 * B_MAT;       // 36864
    constexpr int TSLOT  = 2 * STAGE;

    extern __shared__ char smem[];
    const uint32_t base = smem_u32(smem);

    const int tid  = threadIdx.x;
    const int warp = tid >> 5, lane = tid & 31;
    const int wm = warp & 3, wn = warp >> 2;

    const uint32_t a_row = (uint32_t)(wm * 32 + ((lane >> 3) & 1) * 8 + (lane & 7));
    const uint32_t a_ko  = (uint32_t)((lane >> 4) * 8);
    const uint32_t b_row = (uint32_t)(wn * 32 + (lane >> 4) * 8 + (lane & 7));
    const uint32_t b_ko  = (uint32_t)(((lane >> 3) & 1) * 8);

    for (;;) {
        if (tid == 0)
            *(volatile unsigned int*)(smem + TSLOT) = atomicAdd(&g_ctr[ctr_idx], 1u);
        __syncthreads();
        const unsigned int t = *(volatile unsigned int*)(smem + TSLOT);
        if (t >= (unsigned)ntiles) break;
        const int bm = (int)(t / ntn) * 128;
        const int bn = (int)(t % ntn) * 64;

        auto load_chunk = [&](int c) {
            const uint32_t st = base + (uint32_t)(c & 1) * STAGE;
            const int k0 = c * 64;
            #pragma unroll
            for (int j = 0; j < 4; j++) {
                int g = tid + 256 * j;
                int r = g >> 3, sg = g & 7;
                uint32_t so = (uint32_t)(r * PITCHB + sg * 16);
                cp_async16(st + OFF_A + so,
                           Ahi + (size_t)(bm + r) * K + k0 + sg * 8);
            }
            #pragma unroll
            for (int j = 0; j < 2; j++) {
                int g = tid + 256 * j;
                int r = g >> 3, sg = g & 7;
                uint32_t so = (uint32_t)(r * PITCHB + sg * 16);
                size_t gb = (size_t)(bn + r) * K + k0 + sg * 8;
                cp_async16(st + OFF_BH + so, Bhi + gb);
                cp_async16(st + OFF_BL + so, Blo + gb);
            }
            CP_COMMIT();
        };

        float acc[2][4][4];
        #pragma unroll
        for (int mi = 0; mi < 2; mi++)
            #pragma unroll
            for (int ni = 0; ni < 4; ni++)
                #pragma unroll
                for (int q = 0; q < 4; q++) acc[mi][ni][q] = 0.f;

        const int nch = K / 64;
        load_chunk(0);

        for (int c = 0; c < nch; c++) {
            if (c + 1 < nch) { load_chunk(c + 1); CP_WAIT1(); }
            else             { CP_WAIT0(); }
            __syncthreads();

            const uint32_t st = base + (uint32_t)(c & 1) * STAGE;
            #pragma unroll
            for (int ks = 0; ks < 4; ks++) {
                uint32_t Ah[2][4], Bh[2][4], Bl[2][4];
                #pragma unroll
                for (int mi = 0; mi < 2; mi++) {
                    uint32_t ao = (a_row + mi * 16) * PITCHB + (ks * 16 + a_ko) * 2;
                    LDM4(Ah[mi], st + OFF_A + ao);
                }
                #pragma unroll
                for (int nt = 0; nt < 2; nt++) {
                    uint32_t bo = (b_row + nt * 16) * PITCHB + (ks * 16 + b_ko) * 2;
                    LDM4(Bh[nt], st + OFF_BH + bo);
                    LDM4(Bl[nt], st + OFF_BL + bo);
                }
                // bh sweep (8 independent accs), then bl sweep
                #pragma unroll
                for (int mi = 0; mi < 2; mi++)
                    #pragma unroll
                    for (int ni = 0; ni < 4; ni++)
                        MMA16816(acc[mi][ni], Ah[mi],
                                 Bh[ni >> 1][(ni & 1) * 2],
                                 Bh[ni >> 1][(ni & 1) * 2 + 1]);
                #pragma unroll
                for (int mi = 0; mi < 2; mi++)
                    #pragma unroll
                    for (int ni = 0; ni < 4; ni++)
                        MMA16816(acc[mi][ni], Ah[mi],
                                 Bl[ni >> 1][(ni & 1) * 2],
                                 Bl[ni >> 1][(ni & 1) * 2 + 1]);
            }
            __syncthreads();
        }

        const int r0 = bm + wm * 32 + (lane >> 2);
        const int c0 = bn + wn * 32 + (lane & 3) * 2;
        #pragma unroll
        for (int mi = 0; mi < 2; mi++)
            #pragma unroll
            for (int ni = 0; ni < 4; ni++) {
                int row = r0 + mi * 16;
                int col = c0 + ni * 8;
                float2 b2 = *(const float2*)(bias + col);
                float v0 = acc[mi][ni][0] + b2.x, v1 = acc[mi][ni][1] + b2.y;
                float v2 = acc[mi][ni][2] + b2.x, v3 = acc[mi][ni][3] + b2.y;
                if (!SPLIT_OUT) {
                    *(float2*)(C + (size_t)row * N + col)       = make_float2(v0, v1);
                    *(float2*)(C + (size_t)(row + 8) * N + col) = make_float2(v2, v3);
                } else {
                    *(uint32_t*)(Ch + (size_t)row * N + col)       = pack_h2(v0, v1);
                    *(uint32_t*)(Ch + (size_t)(row + 8) * N + col) = pack_h2(v2, v3);
                }
            }
    }
}

// ---------------------------------------------------------------------------
// Tensor-core flash attention, fp16 single-precision operands throughout:
//   S = Qh*Kh   (1-pass)     O = P*Vh   (1-pass, P single fp16)
// Split-key warp groups + paired q-tiles; emits z hi-only into the
// bug-faithful layout: Z[h*128 + 2*d + (t>>10)][t & 1023] = y[h][t][d]
// ---------------------------------------------------------------------------
__global__ __launch_bounds__(512, 1) void attn_mma(
    const __half* __restrict__ qkvh, __half* __restrict__ Zhi)
{
    constexpr int PITCH = 144;
    constexpr int MAT   = 128 * PITCH;
    constexpr int QH_OFF = 0;
    constexpr int ST0 = MAT;
    constexpr int KH = 0, VH = MAT;
    constexpr int STAGE = 2 * MAT;

    extern __shared__ char smem[];
    const uint32_t base = smem_u32(smem);
    float* mergebuf = (float*)smem;

    const int tid  = threadIdx.x;
    const int warp = tid >> 5, lane = tid & 31;
    const int grp  = warp >> 3;
    const int wg   = warp & 7;
    const int wq   = wg * 16;
    const int kh   = grp * 64;
    const int h    = blockIdx.y;

    const float NEG_INF = __int_as_float(0xff800000);

    const uint32_t a_rl = (uint32_t)(((lane >> 3) & 1) * 8 + (lane & 7));
    const uint32_t a_ko = (uint32_t)((lane >> 4) * 8);
    const uint32_t b_rl = (uint32_t)((lane >> 4) * 8 + (lane & 7));
    const uint32_t b_ko = (uint32_t)(((lane >> 3) & 1) * 8);

    for (int pass = 0; pass < 2; pass++) {
        const int qi = pass == 0 ? (15 - (int)blockIdx.x) : (int)blockIdx.x;

        __syncthreads();

        #pragma unroll
        for (int j = 0; j < 2; j++) {       // Q hi: 1024 segs
            int g = tid + 512 * j;
            int r = g >> 3, sg = g & 7;
            uint32_t so = (uint32_t)(r * PITCH + sg * 16);
            cp_async16(base + QH_OFF + so,
                       qkvh + (size_t)(qi * 128 + r) * QKV_N + h * HDIM + sg * 8);
        }
        auto load_kv = [&](int kt) {
            const uint32_t st = base + ST0 + (uint32_t)(kt & 1) * STAGE;
            #pragma unroll
            for (int j = 0; j < 2; j++) {
                int g = tid + 512 * j;
                int r = g >> 3, sg = g & 7;
                uint32_t so = (uint32_t)(r * PITCH + sg * 16);
                size_t gk = (size_t)(kt * 128 + r) * QKV_N + C_DIM     + h * HDIM + sg * 8;
                size_t gv = (size_t)(kt * 128 + r) * QKV_N + 2 * C_DIM + h * HDIM + sg * 8;
                cp_async16(st + KH + so, qkvh + gk);
                cp_async16(st + VH + so, qkvh + gv);
            }
        };
        load_kv(0);
        CP_COMMIT();

        float m_run[2] = {-1e30f, -1e30f};
        float l_run[2] = {0.f, 0.f};
        float O[8][4];
        #pragma unroll
        for (int a = 0; a < 8; a++)
            #pragma unroll
            for (int q = 0; q < 4; q++) O[a][q] = 0.f;

        for (int kt = 0; kt <= qi; kt++) {
            __syncthreads();
            if (kt + 1 <= qi) { load_kv(kt + 1); CP_COMMIT(); CP_WAIT1(); }
            else              { CP_WAIT0(); }
            __syncthreads();

            const uint32_t sk = base + ST0 + (uint32_t)(kt & 1) * STAGE;

            float S[8][4];
            #pragma unroll
            for (int a = 0; a < 8; a++)
                #pragma unroll
                for (int q = 0; q < 4; q++) S[a][q] = 0.f;

            #pragma unroll
            for (int ks = 0; ks < 4; ks++) {
                uint32_t Ah[4];
                uint32_t ao = (wq + a_rl) * PITCH + (ks * 16 + a_ko) * 2;
                LDM4(Ah, base + QH_OFF + ao);
                #pragma unroll
                for (int ng = 0; ng < 4; ng++) {
                    uint32_t Bh[4];
                    uint32_t bo = (kh + ng * 16 + b_rl) * PITCH + (ks * 16 + b_ko) * 2;
                    LDM4(Bh, sk + KH + bo);
                    MMA16816(S[2*ng],   Ah, Bh[0], Bh[1]);
                    MMA16816(S[2*ng+1], Ah, Bh[2], Bh[3]);
                }
            }
            #pragma unroll
            for (int a = 0; a < 8; a++)
                #pragma unroll
                for (int q = 0; q < 4; q++) S[a][q] *= 0.125f;

            if (kt == qi) {
                int rbase = qi * 128 + wq + (lane >> 2);
                int cbase = kt * 128 + kh + (lane & 3) * 2;
                #pragma unroll
                for (int a = 0; a < 8; a++)
                    #pragma unroll
                    for (int q = 0; q < 4; q++) {
                        int row = rbase + (q >= 2 ? 8 : 0);
                        int col = cbase + a * 8 + (q & 1);
                        if (col > row) S[a][q] = NEG_INF;
                    }
            }

            #pragma unroll
            for (int i = 0; i < 2; i++) {
                float mx = NEG_INF;
                #pragma unroll
                for (int a = 0; a < 8; a++)
                    mx = fmaxf(mx, fmaxf(S[a][2*i], S[a][2*i+1]));
                mx = fmaxf(mx, __shfl_xor_sync(0xffffffffu, mx, 1));
                mx = fmaxf(mx, __shfl_xor_sync(0xffffffffu, mx, 2));
                float mn = fmaxf(m_run[i], mx);
                float alpha = __expf(m_run[i] - mn);
                float sum = 0.f;
                #pragma unroll
                for (int a = 0; a < 8; a++) {
                    float p0 = __expf(S[a][2*i]   - mn);
                    float p1 = __expf(S[a][2*i+1] - mn);
                    S[a][2*i] = p0; S[a][2*i+1] = p1;
                    sum += p0 + p1;
                }
                sum += __shfl_xor_sync(0xffffffffu, sum, 1);
                sum += __shfl_xor_sync(0xffffffffu, sum, 2);
                l_run[i] = l_run[i] * alpha + sum;
                m_run[i] = mn;
                #pragma unroll
                for (int a = 0; a < 8; a++) {
                    O[a][2*i]   *= alpha;
                    O[a][2*i+1] *= alpha;
                }
            }

            uint32_t Ph[4][4];
            #pragma unroll
            for (int kc = 0; kc < 4; kc++) {
                Ph[kc][0] = pack_h2(S[2*kc][0],   S[2*kc][1]);
                Ph[kc][1] = pack_h2(S[2*kc][2],   S[2*kc][3]);
                Ph[kc][2] = pack_h2(S[2*kc+1][0], S[2*kc+1][1]);
                Ph[kc][3] = pack_h2(S[2*kc+1][2], S[2*kc+1][3]);
            }

            #pragma unroll
            for (int kc = 0; kc < 4; kc++) {
                uint32_t krow = (uint32_t)(kh + kc * 16) + a_rl;
                #pragma unroll
                for (int dg = 0; dg < 4; dg++) {
                    uint32_t Vh4[4];
                    uint32_t vo = krow * PITCH + (dg * 16 + a_ko) * 2;
                    LDMT4(Vh4, sk + VH + vo);
                    MMA16816(O[2*dg],   Ph[kc], Vh4[0], Vh4[1]);
                    MMA16816(O[2*dg+1], Ph[kc], Vh4[2], Vh4[3]);
                }
            }
        }

        __syncthreads();
        const int slot = wg * 32 + lane;
        float* buf = mergebuf + slot * 37;
        if (grp == 1) {
            buf[0] = m_run[0]; buf[1] = m_run[1];
            buf[2] = l_run[0]; buf[3] = l_run[1];
            #pragma unroll
            for (int a = 0; a < 8; a++)
                #pragma unroll
                for (int q = 0; q < 4; q++) buf[4 + a * 4 + q] = O[a][q];
        }
        __syncthreads();
        if (grp == 0) {
            #pragma unroll
            for (int i = 0; i < 2; i++) {
                float m1 = buf[i], l1 = buf[2 + i];
                float m = fmaxf(m_run[i], m1);
                float a0 = __expf(m_run[i] - m);
                float a1 = __expf(m1 - m);
                l_run[i] = l_run[i] * a0 + l1 * a1;
                #pragma unroll
                for (int a = 0; a < 8; a++)
                    #pragma unroll
                    for (int q = 0; q < 2; q++)
                        O[a][2*i + q] = O[a][2*i + q] * a0
                                      + buf[4 + a * 4 + 2*i + q] * a1;
            }
            #pragma unroll
            for (int i = 0; i < 2; i++) {
                float inv = 1.0f / l_run[i];
                int t   = qi * 128 + wq + (lane >> 2) + 8 * i;
                int col = t & (C_DIM - 1);
                int thi = t >> 10;
                #pragma unroll
                for (int a = 0; a < 8; a++)
                    #pragma unroll
                    for (int q = 0; q < 2; q++) {
                        int d = a * 8 + (lane & 3) * 2 + q;
                        float v = O[a][2*i + q] * inv;
                        int row = h * 128 + 2 * d + thi;
                        Zhi[(size_t)row * C_DIM + col] = __float2half_rn(v);
                    }
            }
        }
    }
}

// ---------------------------------------------------------------------------
extern "C" void kernel_launch(void* const* d_in, const int* in_sizes, int n_in,
                              void* d_out, int out_size)
{
    const float* x      = (const float*)d_in[0];
    const float* w_attn = (const float*)d_in[1];
    const float* b_attn = (const float*)d_in[2];
    const float* w_proj = (const float*)d_in[3];
    const float* b_proj = (const float*)d_in[4];
    float* out = (float*)d_out;

    void *p;
    cudaGetSymbolAddress(&p, g_qkvh); __half* qh = (__half*)p;
    cudaGetSymbolAddress(&p, g_xh);   __half* xh = (__half*)p;
    cudaGetSymbolAddress(&p, g_wah);  __half* wah = (__half*)p;
    cudaGetSymbolAddress(&p, g_wal);  __half* wal = (__half*)p;
    cudaGetSymbolAddress(&p, g_wph);  __half* wph = (__half*)p;
    cudaGetSymbolAddress(&p, g_wpl);  __half* wpl = (__half*)p;
    cudaGetSymbolAddress(&p, g_zh);   __half* zh = (__half*)p;

    // 0) splits (x hi-only also resets tile counters)
    split_hi<<<(T_DIM * C_DIM) / 1024, 256>>>(x, xh, T_DIM * C_DIM);
    split_f32<<<(QKV_N * C_DIM) / 1024, 256>>>(w_attn, wah, wal, QKV_N * C_DIM);
    split_f32<<<(C_DIM * C_DIM) / 1024, 256>>>(w_proj, wph, wpl, C_DIM * C_DIM);

    constexpr int GEMM_SMEM = 2 * (128 * 144 + 2 * 64 * 144) + 16;  // 73744
    cudaFuncSetAttribute(gemm_mma_fp16x2<true>,
                         cudaFuncAttributeMaxDynamicSharedMemorySize, GEMM_SMEM);
    cudaFuncSetAttribute(gemm_mma_fp16x2<false>,
                         cudaFuncAttributeMaxDynamicSharedMemorySize, GEMM_SMEM);

    // 1) QKV projection -> single-fp16 qkv (persistent, counter 0)
    gemm_mma_fp16x2<true><<<296, 256, GEMM_SMEM>>>(
        xh, wah, wal, b_attn, nullptr, qh,
        QKV_N, C_DIM, QKV_N / 64, (T_DIM / 128) * (QKV_N / 64), 0);

    // 2) Tensor-core flash attention -> z hi-only (fused permute)
    {
        constexpr int ATTN_SMEM = 5 * 128 * 144;   // 92160 B
        cudaFuncSetAttribute(attn_mma,
                             cudaFuncAttributeMaxDynamicSharedMemorySize, ATTN_SMEM);
        dim3 grid(T_DIM / 256, NHEAD);
        attn_mma<<<grid, 512, ATTN_SMEM>>>(qh, zh);
    }

    // 3) Output projection (persistent, counter 1, fp32 out)
    gemm_mma_fp16x2<false><<<296, 256, GEMM_SMEM>>>(
        zh, wph, wpl, b_proj, out, nullptr,
        C_DIM, C_DIM, C_DIM / 64, (T_DIM / 128) * (C_DIM / 64), 1);
}

// round 17
// speedup vs baseline: 4.8438x; 1.0531x over previous
#include <cuda_runtime.h>
#include <cuda_fp16.h>
#include <cstdint>

#define T_DIM 2048
#define C_DIM 1024
#define NHEAD 16
#define HDIM  64
#define QKV_N (3 * C_DIM)

// ---------------------------------------------------------------------------
// Scratch (__device__ globals; allocation-free rule)
// ---------------------------------------------------------------------------
__device__ __half g_qkvh[T_DIM * QKV_N];
__device__ __half g_xh[T_DIM * C_DIM];
__device__ __half g_wah[QKV_N * C_DIM], g_wal[QKV_N * C_DIM];
__device__ __half g_wph[C_DIM * C_DIM], g_wpl[C_DIM * C_DIM];
__device__ __half g_zh[T_DIM * C_DIM];
__device__ unsigned int g_ctr[2];

// ---------------------------------------------------------------------------
// PTX helpers — sm_80-era only (harness stages PTX at compute_103)
// ---------------------------------------------------------------------------
__device__ __forceinline__ uint32_t smem_u32(const void* p) {
    uint32_t a;
    asm("{ .reg .u64 t; cvta.to.shared.u64 t, %1; cvt.u32.u64 %0, t; }"
        : "=r"(a) : "l"(p));
    return a;
}
__device__ __forceinline__ void cp_async16(uint32_t s, const void* g) {
    asm volatile("cp.async.cg.shared.global [%0], [%1], 16;" :: "r"(s), "l"(g));
}
#define CP_COMMIT() asm volatile("cp.async.commit_group;" ::: "memory")
#define CP_WAIT1()  asm volatile("cp.async.wait_group 1;" ::: "memory")
#define CP_WAIT0()  asm volatile("cp.async.wait_group 0;" ::: "memory")

#define LDM4(R, addr) \
    asm volatile("ldmatrix.sync.aligned.m8n8.x4.shared.b16 {%0,%1,%2,%3}, [%4];" \
        : "=r"((R)[0]), "=r"((R)[1]), "=r"((R)[2]), "=r"((R)[3]) : "r"(addr))
#define LDMT4(R, addr) \
    asm volatile("ldmatrix.sync.aligned.m8n8.x4.trans.shared.b16 {%0,%1,%2,%3}, [%4];" \
        : "=r"((R)[0]), "=r"((R)[1]), "=r"((R)[2]), "=r"((R)[3]) : "r"(addr))

#define MMA16816(c, a, b0, b1) \
    asm volatile("mma.sync.aligned.m16n8k16.row.col.f32.f16.f16.f32 " \
        "{%0,%1,%2,%3}, {%4,%5,%6,%7}, {%8,%9}, {%0,%1,%2,%3};" \
        : "+f"((c)[0]), "+f"((c)[1]), "+f"((c)[2]), "+f"((c)[3]) \
        : "r"((a)[0]), "r"((a)[1]), "r"((a)[2]), "r"((a)[3]), "r"(b0), "r"(b1))

__device__ __forceinline__ uint32_t pack_h2(float x, float y) {
    __half hx = __float2half_rn(x), hy = __float2half_rn(y);
    uint16_t ux = *(uint16_t*)&hx, uy = *(uint16_t*)&hy;
    return (uint32_t)ux | ((uint32_t)uy << 16);
}

// ---------------------------------------------------------------------------
// fp32 -> fp16 hi-only split (A-side operands); also resets tile counters
__global__ __launch_bounds__(256) void split_hi(
    const float* __restrict__ src, __half* __restrict__ hi, int n)
{
    if (blockIdx.x == 0 && threadIdx.x == 0) { g_ctr[0] = 0; g_ctr[1] = 0; }
    int i = (blockIdx.x * 256 + threadIdx.x) * 4;
    if (i >= n) return;
    float4 v = *(const float4*)(src + i);
    __half2* h2 = (__half2*)(hi + i);
    h2[0] = __floats2half2_rn(v.x, v.y);
    h2[1] = __floats2half2_rn(v.z, v.w);
}

// fp32 -> (hi, lo) fp16 split (weights / B-side)
__global__ __launch_bounds__(256) void split_f32(
    const float* __restrict__ src, __half* __restrict__ hi,
    __half* __restrict__ lo, int n)
{
    int i = (blockIdx.x * 256 + threadIdx.x) * 4;
    if (i >= n) return;
    float4 v = *(const float4*)(src + i);
    float vv[4] = {v.x, v.y, v.z, v.w};
    #pragma unroll
    for (int j = 0; j < 4; j++) {
        __half h = __float2half_rn(vv[j]);
        hi[i + j] = h;
        lo[i + j] = __float2half_rn(vv[j] - __half2float(h));
    }
}

// ---------------------------------------------------------------------------
// Persistent 128x128-tile NT GEMM, 2-pass: D = Ah*(Bh + Bl) + bias.
// 256 threads, 8 warps as 4m x 2n (warp tile 32x64), 2 CTAs/SM.
// Arithmetic intensity doubled vs 128x64 -> tensor pipe becomes binding.
// B fragments processed in two n-halves to cap register pressure.
// SPLIT_OUT=true: single-fp16 output Ch.
// ---------------------------------------------------------------------------
template <bool SPLIT_OUT>
__global__ __launch_bounds__(256, 2) void gemm_bn128(
    const __half* __restrict__ Ahi,
    const __half* __restrict__ Bhi, const __half* __restrict__ Blo,
    const float* __restrict__ bias, float* __restrict__ C,
    __half* __restrict__ Ch,
    int N, int K, int ntn, int ntiles, int ctr_idx)
{
    constexpr int PITCHB = 144;
    constexpr int MATB   = 128 * PITCHB;            // 18432
    constexpr int OFF_A  = 0, OFF_BH = MATB, OFF_BL = 2 * MATB;
    constexpr int STAGE  = 3 * MATB;                // 55296
    constexpr int TSLOT  = 2 * STAGE;

    extern __shared__ char smem[];
    const uint32_t base = smem_u32(smem);

    const int tid  = threadIdx.x;
    const int warp = tid >> 5, lane = tid & 31;
    const int wm = warp & 3, wn = warp >> 2;        // 4m x 2n

    const uint32_t a_row = (uint32_t)(wm * 32 + ((lane >> 3) & 1) * 8 + (lane & 7));
    const uint32_t a_ko  = (uint32_t)((lane >> 4) * 8);
    const uint32_t b_row = (uint32_t)(wn * 64 + (lane >> 4) * 8 + (lane & 7));
    const uint32_t b_ko  = (uint32_t)(((lane >> 3) & 1) * 8);

    for (;;) {
        if (tid == 0)
            *(volatile unsigned int*)(smem + TSLOT) = atomicAdd(&g_ctr[ctr_idx], 1u);
        __syncthreads();
        const unsigned int t = *(volatile unsigned int*)(smem + TSLOT);
        if (t >= (unsigned)ntiles) break;
        const int bm = (int)(t / ntn) * 128;
        const int bn = (int)(t % ntn) * 128;

        auto load_chunk = [&](int c) {
            const uint32_t st = base + (uint32_t)(c & 1) * STAGE;
            const int k0 = c * 64;
            #pragma unroll
            for (int j = 0; j < 4; j++) {            // 1024 segs per matrix
                int g = tid + 256 * j;
                int r = g >> 3, sg = g & 7;
                uint32_t so = (uint32_t)(r * PITCHB + sg * 16);
                size_t ga = (size_t)(bm + r) * K + k0 + sg * 8;
                size_t gb = (size_t)(bn + r) * K + k0 + sg * 8;
                cp_async16(st + OFF_A  + so, Ahi + ga);
                cp_async16(st + OFF_BH + so, Bhi + gb);
                cp_async16(st + OFF_BL + so, Blo + gb);
            }
            CP_COMMIT();
        };

        float acc[2][8][4];
        #pragma unroll
        for (int mi = 0; mi < 2; mi++)
            #pragma unroll
            for (int ni = 0; ni < 8; ni++)
                #pragma unroll
                for (int q = 0; q < 4; q++) acc[mi][ni][q] = 0.f;

        const int nch = K / 64;
        load_chunk(0);

        for (int c = 0; c < nch; c++) {
            if (c + 1 < nch) { load_chunk(c + 1); CP_WAIT1(); }
            else             { CP_WAIT0(); }
            __syncthreads();

            const uint32_t st = base + (uint32_t)(c & 1) * STAGE;
            #pragma unroll
            for (int ks = 0; ks < 4; ks++) {
                uint32_t Ah[2][4];
                #pragma unroll
                for (int mi = 0; mi < 2; mi++) {
                    uint32_t ao = (a_row + mi * 16) * PITCHB + (ks * 16 + a_ko) * 2;
                    LDM4(Ah[mi], st + OFF_A + ao);
                }
                // two n-halves: reuse B registers, keep acc reuse distance 8
                #pragma unroll
                for (int hf = 0; hf < 2; hf++) {
                    uint32_t Bh[2][4], Bl[2][4];
                    #pragma unroll
                    for (int nt = 0; nt < 2; nt++) {
                        uint32_t bo = (b_row + (hf * 2 + nt) * 16) * PITCHB
                                    + (ks * 16 + b_ko) * 2;
                        LDM4(Bh[nt], st + OFF_BH + bo);
                        LDM4(Bl[nt], st + OFF_BL + bo);
                    }
                    #pragma unroll
                    for (int mi = 0; mi < 2; mi++)
                        #pragma unroll
                        for (int ni = 0; ni < 4; ni++)
                            MMA16816(acc[mi][hf * 4 + ni], Ah[mi],
                                     Bh[ni >> 1][(ni & 1) * 2],
                                     Bh[ni >> 1][(ni & 1) * 2 + 1]);
                    #pragma unroll
                    for (int mi = 0; mi < 2; mi++)
                        #pragma unroll
                        for (int ni = 0; ni < 4; ni++)
                            MMA16816(acc[mi][hf * 4 + ni], Ah[mi],
                                     Bl[ni >> 1][(ni & 1) * 2],
                                     Bl[ni >> 1][(ni & 1) * 2 + 1]);
                }
            }
            __syncthreads();
        }

        const int r0 = bm + wm * 32 + (lane >> 2);
        const int c0 = bn + wn * 64 + (lane & 3) * 2;
        #pragma unroll
        for (int mi = 0; mi < 2; mi++)
            #pragma unroll
            for (int ni = 0; ni < 8; ni++) {
                int row = r0 + mi * 16;
                int col = c0 + ni * 8;
                float2 b2 = *(const float2*)(bias + col);
                float v0 = acc[mi][ni][0] + b2.x, v1 = acc[mi][ni][1] + b2.y;
                float v2 = acc[mi][ni][2] + b2.x, v3 = acc[mi][ni][3] + b2.y;
                if (!SPLIT_OUT) {
                    *(float2*)(C + (size_t)row * N + col)       = make_float2(v0, v1);
                    *(float2*)(C + (size_t)(row + 8) * N + col) = make_float2(v2, v3);
                } else {
                    *(uint32_t*)(Ch + (size_t)row * N + col)       = pack_h2(v0, v1);
                    *(uint32_t*)(Ch + (size_t)(row + 8) * N + col) = pack_h2(v2, v3);
                }
            }
    }
}

// ---------------------------------------------------------------------------
// Persistent 128x64-tile NT GEMM (2-pass) — kept for proj (256 tiles > 128).
// ---------------------------------------------------------------------------
template <bool SPLIT_OUT>
__global__ __launch_bounds__(256, 2) void gemm_bn64(
    const __half* __restrict__ Ahi,
    const __half* __restrict__ Bhi, const __half* __restrict__ Blo,
    const float* __restrict__ bias, float* __restrict__ C,
    __half* __restrict__ Ch,
    int N, int K, int ntn, int ntiles, int ctr_idx)
{
    constexpr int PITCHB = 144;
    constexpr int A_MAT  = 128 * PITCHB;
    constexpr int B_MAT  = 64 * PITCHB;
    constexpr int OFF_A  = 0;
    constexpr int OFF_BH = A_MAT, OFF_BL = A_MAT + B_MAT;
    constexpr int STAGE  = A_MAT + 2 * B_MAT;
    constexpr int TSLOT  = 2 * STAGE;

    extern __shared__ char smem[];
    const uint32_t base = smem_u32(smem);

    const int tid  = threadIdx.x;
    const int warp = tid >> 5, lane = tid & 31;
    const int wm = warp & 3, wn = warp >> 2;

    const uint32_t a_row = (uint32_t)(wm * 32 + ((lane >> 3) & 1) * 8 + (lane & 7));
    const uint32_t a_ko  = (uint32_t)((lane >> 4) * 8);
    const uint32_t b_row = (uint32_t)(wn * 32 + (lane >> 4) * 8 + (lane & 7));
    const uint32_t b_ko  = (uint32_t)(((lane >> 3) & 1) * 8);

    for (;;) {
        if (tid == 0)
            *(volatile unsigned int*)(smem + TSLOT) = atomicAdd(&g_ctr[ctr_idx], 1u);
        __syncthreads();
        const unsigned int t = *(volatile unsigned int*)(smem + TSLOT);
        if (t >= (unsigned)ntiles) break;
        const int bm = (int)(t / ntn) * 128;
        const int bn = (int)(t % ntn) * 64;

        auto load_chunk = [&](int c) {
            const uint32_t st = base + (uint32_t)(c & 1) * STAGE;
            const int k0 = c * 64;
            #pragma unroll
            for (int j = 0; j < 4; j++) {
                int g = tid + 256 * j;
                int r = g >> 3, sg = g & 7;
                uint32_t so = (uint32_t)(r * PITCHB + sg * 16);
                cp_async16(st + OFF_A + so,
                           Ahi + (size_t)(bm + r) * K + k0 + sg * 8);
            }
            #pragma unroll
            for (int j = 0; j < 2; j++) {
                int g = tid + 256 * j;
                int r = g >> 3, sg = g & 7;
                uint32_t so = (uint32_t)(r * PITCHB + sg * 16);
                size_t gb = (size_t)(bn + r) * K + k0 + sg * 8;
                cp_async16(st + OFF_BH + so, Bhi + gb);
                cp_async16(st + OFF_BL + so, Blo + gb);
            }
            CP_COMMIT();
        };

        float acc[2][4][4];
        #pragma unroll
        for (int mi = 0; mi < 2; mi++)
            #pragma unroll
            for (int ni = 0; ni < 4; ni++)
                #pragma unroll
                for (int q = 0; q < 4; q++) acc[mi][ni][q] = 0.f;

        const int nch = K / 64;
        load_chunk(0);

        for (int c = 0; c < nch; c++) {
            if (c + 1 < nch) { load_chunk(c + 1); CP_WAIT1(); }
            else             { CP_WAIT0(); }
            __syncthreads();

            const uint32_t st = base + (uint32_t)(c & 1) * STAGE;
            #pragma unroll
            for (int ks = 0; ks < 4; ks++) {
                uint32_t Ah[2][4], Bh[2][4], Bl[2][4];
                #pragma unroll
                for (int mi = 0; mi < 2; mi++) {
                    uint32_t ao = (a_row + mi * 16) * PITCHB + (ks * 16 + a_ko) * 2;
                    LDM4(Ah[mi], st + OFF_A + ao);
                }
                #pragma unroll
                for (int nt = 0; nt < 2; nt++) {
                    uint32_t bo = (b_row + nt * 16) * PITCHB + (ks * 16 + b_ko) * 2;
                    LDM4(Bh[nt], st + OFF_BH + bo);
                    LDM4(Bl[nt], st + OFF_BL + bo);
                }
                #pragma unroll
                for (int mi = 0; mi < 2; mi++)
                    #pragma unroll
                    for (int ni = 0; ni < 4; ni++)
                        MMA16816(acc[mi][ni], Ah[mi],
                                 Bh[ni >> 1][(ni & 1) * 2],
                                 Bh[ni >> 1][(ni & 1) * 2 + 1]);
                #pragma unroll
                for (int mi = 0; mi < 2; mi++)
                    #pragma unroll
                    for (int ni = 0; ni < 4; ni++)
                        MMA16816(acc[mi][ni], Ah[mi],
                                 Bl[ni >> 1][(ni & 1) * 2],
                                 Bl[ni >> 1][(ni & 1) * 2 + 1]);
            }
            __syncthreads();
        }

        const int r0 = bm + wm * 32 + (lane >> 2);
        const int c0 = bn + wn * 32 + (lane & 3) * 2;
        #pragma unroll
        for (int mi = 0; mi < 2; mi++)
            #pragma unroll
            for (int ni = 0; ni < 4; ni++) {
                int row = r0 + mi * 16;
                int col = c0 + ni * 8;
                float2 b2 = *(const float2*)(bias + col);
                float v0 = acc[mi][ni][0] + b2.x, v1 = acc[mi][ni][1] + b2.y;
                float v2 = acc[mi][ni][2] + b2.x, v3 = acc[mi][ni][3] + b2.y;
                if (!SPLIT_OUT) {
                    *(float2*)(C + (size_t)row * N + col)       = make_float2(v0, v1);
                    *(float2*)(C + (size_t)(row + 8) * N + col) = make_float2(v2, v3);
                } else {
                    *(uint32_t*)(Ch + (size_t)row * N + col)       = pack_h2(v0, v1);
                    *(uint32_t*)(Ch + (size_t)(row + 8) * N + col) = pack_h2(v2, v3);
                }
            }
    }
}

// ---------------------------------------------------------------------------
// Tensor-core flash attention, fp16 1-pass S and O.
// Split-key warp groups + paired q-tiles; emits z hi-only into the
// bug-faithful layout: Z[h*128 + 2*d + (t>>10)][t & 1023] = y[h][t][d]
// ---------------------------------------------------------------------------
__global__ __launch_bounds__(512, 1) void attn_mma(
    const __half* __restrict__ qkvh, __half* __restrict__ Zhi)
{
    constexpr int PITCH = 144;
    constexpr int MAT   = 128 * PITCH;
    constexpr int QH_OFF = 0;
    constexpr int ST0 = MAT;
    constexpr int KH = 0, VH = MAT;
    constexpr int STAGE = 2 * MAT;

    extern __shared__ char smem[];
    const uint32_t base = smem_u32(smem);
    float* mergebuf = (float*)smem;

    const int tid  = threadIdx.x;
    const int warp = tid >> 5, lane = tid & 31;
    const int grp  = warp >> 3;
    const int wg   = warp & 7;
    const int wq   = wg * 16;
    const int kh   = grp * 64;
    const int h    = blockIdx.y;

    const float NEG_INF = __int_as_float(0xff800000);

    const uint32_t a_rl = (uint32_t)(((lane >> 3) & 1) * 8 + (lane & 7));
    const uint32_t a_ko = (uint32_t)((lane >> 4) * 8);
    const uint32_t b_rl = (uint32_t)((lane >> 4) * 8 + (lane & 7));
    const uint32_t b_ko = (uint32_t)(((lane >> 3) & 1) * 8);

    for (int pass = 0; pass < 2; pass++) {
        const int qi = pass == 0 ? (15 - (int)blockIdx.x) : (int)blockIdx.x;

        __syncthreads();

        #pragma unroll
        for (int j = 0; j < 2; j++) {
            int g = tid + 512 * j;
            int r = g >> 3, sg = g & 7;
            uint32_t so = (uint32_t)(r * PITCH + sg * 16);
            cp_async16(base + QH_OFF + so,
                       qkvh + (size_t)(qi * 128 + r) * QKV_N + h * HDIM + sg * 8);
        }
        auto load_kv = [&](int kt) {
            const uint32_t st = base + ST0 + (uint32_t)(kt & 1) * STAGE;
            #pragma unroll
            for (int j = 0; j < 2; j++) {
                int g = tid + 512 * j;
                int r = g >> 3, sg = g & 7;
                uint32_t so = (uint32_t)(r * PITCH + sg * 16);
                size_t gk = (size_t)(kt * 128 + r) * QKV_N + C_DIM     + h * HDIM + sg * 8;
                size_t gv = (size_t)(kt * 128 + r) * QKV_N + 2 * C_DIM + h * HDIM + sg * 8;
                cp_async16(st + KH + so, qkvh + gk);
                cp_async16(st + VH + so, qkvh + gv);
            }
        };
        load_kv(0);
        CP_COMMIT();

        float m_run[2] = {-1e30f, -1e30f};
        float l_run[2] = {0.f, 0.f};
        float O[8][4];
        #pragma unroll
        for (int a = 0; a < 8; a++)
            #pragma unroll
            for (int q = 0; q < 4; q++) O[a][q] = 0.f;

        for (int kt = 0; kt <= qi; kt++) {
            __syncthreads();
            if (kt + 1 <= qi) { load_kv(kt + 1); CP_COMMIT(); CP_WAIT1(); }
            else              { CP_WAIT0(); }
            __syncthreads();

            const uint32_t sk = base + ST0 + (uint32_t)(kt & 1) * STAGE;

            float S[8][4];
            #pragma unroll
            for (int a = 0; a < 8; a++)
                #pragma unroll
                for (int q = 0; q < 4; q++) S[a][q] = 0.f;

            #pragma unroll
            for (int ks = 0; ks < 4; ks++) {
                uint32_t Ah[4];
                uint32_t ao = (wq + a_rl) * PITCH + (ks * 16 + a_ko) * 2;
                LDM4(Ah, base + QH_OFF + ao);
                #pragma unroll
                for (int ng = 0; ng < 4; ng++) {
                    uint32_t Bh[4];
                    uint32_t bo = (kh + ng * 16 + b_rl) * PITCH + (ks * 16 + b_ko) * 2;
                    LDM4(Bh, sk + KH + bo);
                    MMA16816(S[2*ng],   Ah, Bh[0], Bh[1]);
                    MMA16816(S[2*ng+1], Ah, Bh[2], Bh[3]);
                }
            }
            #pragma unroll
            for (int a = 0; a < 8; a++)
                #pragma unroll
                for (int q = 0; q < 4; q++) S[a][q] *= 0.125f;

            if (kt == qi) {
                int rbase = qi * 128 + wq + (lane >> 2);
                int cbase = kt * 128 + kh + (lane & 3) * 2;
                #pragma unroll
                for (int a = 0; a < 8; a++)
                    #pragma unroll
                    for (int q = 0; q < 4; q++) {
                        int row = rbase + (q >= 2 ? 8 : 0);
                        int col = cbase + a * 8 + (q & 1);
                        if (col > row) S[a][q] = NEG_INF;
                    }
            }

            #pragma unroll
            for (int i = 0; i < 2; i++) {
                float mx = NEG_INF;
                #pragma unroll
                for (int a = 0; a < 8; a++)
                    mx = fmaxf(mx, fmaxf(S[a][2*i], S[a][2*i+1]));
                mx = fmaxf(mx, __shfl_xor_sync(0xffffffffu, mx, 1));
                mx = fmaxf(mx, __shfl_xor_sync(0xffffffffu, mx, 2));
                float mn = fmaxf(m_run[i], mx);
                float alpha = __expf(m_run[i] - mn);
                float sum = 0.f;
                #pragma unroll
                for (int a = 0; a < 8; a++) {
                    float p0 = __expf(S[a][2*i]   - mn);
                    float p1 = __expf(S[a][2*i+1] - mn);
                    S[a][2*i] = p0; S[a][2*i+1] = p1;
                    sum += p0 + p1;
                }
                sum += __shfl_xor_sync(0xffffffffu, sum, 1);
                sum += __shfl_xor_sync(0xffffffffu, sum, 2);
                l_run[i] = l_run[i] * alpha + sum;
                m_run[i] = mn;
                #pragma unroll
                for (int a = 0; a < 8; a++) {
                    O[a][2*i]   *= alpha;
                    O[a][2*i+1] *= alpha;
                }
            }

            uint32_t Ph[4][4];
            #pragma unroll
            for (int kc = 0; kc < 4; kc++) {
                Ph[kc][0] = pack_h2(S[2*kc][0],   S[2*kc][1]);
                Ph[kc][1] = pack_h2(S[2*kc][2],   S[2*kc][3]);
                Ph[kc][2] = pack_h2(S[2*kc+1][0], S[2*kc+1][1]);
                Ph[kc][3] = pack_h2(S[2*kc+1][2], S[2*kc+1][3]);
            }

            #pragma unroll
            for (int kc = 0; kc < 4; kc++) {
                uint32_t krow = (uint32_t)(kh + kc * 16) + a_rl;
                #pragma unroll
                for (int dg = 0; dg < 4; dg++) {
                    uint32_t Vh4[4];
                    uint32_t vo = krow * PITCH + (dg * 16 + a_ko) * 2;
                    LDMT4(Vh4, sk + VH + vo);
                    MMA16816(O[2*dg],   Ph[kc], Vh4[0], Vh4[1]);
                    MMA16816(O[2*dg+1], Ph[kc], Vh4[2], Vh4[3]);
                }
            }
        }

        __syncthreads();
        const int slot = wg * 32 + lane;
        float* buf = mergebuf + slot * 37;
        if (grp == 1) {
            buf[0] = m_run[0]; buf[1] = m_run[1];
            buf[2] = l_run[0]; buf[3] = l_run[1];
            #pragma unroll
            for (int a = 0; a < 8; a++)
                #pragma unroll
                for (int q = 0; q < 4; q++) buf[4 + a * 4 + q] = O[a][q];
        }
        __syncthreads();
        if (grp == 0) {
            #pragma unroll
            for (int i = 0; i < 2; i++) {
                float m1 = buf[i], l1 = buf[2 + i];
                float m = fmaxf(m_run[i], m1);
                float a0 = __expf(m_run[i] - m);
                float a1 = __expf(m1 - m);
                l_run[i] = l_run[i] * a0 + l1 * a1;
                #pragma unroll
                for (int a = 0; a < 8; a++)
                    #pragma unroll
                    for (int q = 0; q < 2; q++)
                        O[a][2*i + q] = O[a][2*i + q] * a0
                                      + buf[4 + a * 4 + 2*i + q] * a1;
            }
            #pragma unroll
            for (int i = 0; i < 2; i++) {
                float inv = 1.0f / l_run[i];
                int t   = qi * 128 + wq + (lane >> 2) + 8 * i;
                int col = t & (C_DIM - 1);
                int thi = t >> 10;
                #pragma unroll
                for (int a = 0; a < 8; a++)
                    #pragma unroll
                    for (int q = 0; q < 2; q++) {
                        int d = a * 8 + (lane & 3) * 2 + q;
                        float v = O[a][2*i + q] * inv;
                        int row = h * 128 + 2 * d + thi;
                        Zhi[(size_t)row * C_DIM + col] = __float2half_rn(v);
                    }
            }
        }
    }
}

// ---------------------------------------------------------------------------
extern "C" void kernel_launch(void* const* d_in, const int* in_sizes, int n_in,
                              void* d_out, int out_size)
{
    const float* x      = (const float*)d_in[0];
    const float* w_attn = (const float*)d_in[1];
    const float* b_attn = (const float*)d_in[2];
    const float* w_proj = (const float*)d_in[3];
    const float* b_proj = (const float*)d_in[4];
    float* out = (float*)d_out;

    void *p;
    cudaGetSymbolAddress(&p, g_qkvh); __half* qh = (__half*)p;
    cudaGetSymbolAddress(&p, g_xh);   __half* xh = (__half*)p;
    cudaGetSymbolAddress(&p, g_wah);  __half* wah = (__half*)p;
    cudaGetSymbolAddress(&p, g_wal);  __half* wal = (__half*)p;
    cudaGetSymbolAddress(&p, g_wph);  __half* wph = (__half*)p;
    cudaGetSymbolAddress(&p, g_wpl);  __half* wpl = (__half*)p;
    cudaGetSymbolAddress(&p, g_zh);   __half* zh = (__half*)p;

    // 0) splits (x hi-only also resets tile counters)
    split_hi<<<(T_DIM * C_DIM) / 1024, 256>>>(x, xh, T_DIM * C_DIM);
    split_f32<<<(QKV_N * C_DIM) / 1024, 256>>>(w_attn, wah, wal, QKV_N * C_DIM);
    split_f32<<<(C_DIM * C_DIM) / 1024, 256>>>(w_proj, wph, wpl, C_DIM * C_DIM);

    constexpr int SMEM128 = 2 * 3 * 128 * 144 + 16;              // 110608
    constexpr int SMEM64  = 2 * (128 * 144 + 2 * 64 * 144) + 16; // 73744
    cudaFuncSetAttribute(gemm_bn128<true>,
                         cudaFuncAttributeMaxDynamicSharedMemorySize, SMEM128);
    cudaFuncSetAttribute(gemm_bn64<false>,
                         cudaFuncAttributeMaxDynamicSharedMemorySize, SMEM64);

    // 1) QKV projection -> single-fp16 qkv (128x128 tiles, counter 0)
    gemm_bn128<true><<<296, 256, SMEM128>>>(
        xh, wah, wal, b_attn, nullptr, qh,
        QKV_N, C_DIM, QKV_N / 128, (T_DIM / 128) * (QKV_N / 128), 0);

    // 2) Tensor-core flash attention -> z hi-only (fused permute)
    {
        constexpr int ATTN_SMEM = 5 * 128 * 144;   // 92160 B
        cudaFuncSetAttribute(attn_mma,
                             cudaFuncAttributeMaxDynamicSharedMemorySize, ATTN_SMEM);
        dim3 grid(T_DIM / 256, NHEAD);
        attn_mma<<<grid, 512, ATTN_SMEM>>>(qh, zh);
    }

    // 3) Output projection (128x64 tiles, counter 1, fp32 out)
    gemm_bn64<false><<<296, 256, SMEM64>>>(
        zh, wph, wpl, b_proj, out, nullptr,
        C_DIM, C_DIM, C_DIM / 64, (T_DIM / 128) * (C_DIM / 64), 1);
}